// round 1
// baseline (speedup 1.0000x reference)
#include <cuda_runtime.h>
#include <mma.h>

using namespace nvcuda;

#define B_  4
#define S_  2048
#define D_  1024
#define H_  16
#define HD  64

// Scratch (allocation-free per harness rules)
__device__ float g_q[B_ * H_ * S_ * HD];   // [B,H,S,Hd]
__device__ float g_k[B_ * H_ * S_ * HD];
__device__ float g_v[B_ * H_ * S_ * HD];
__device__ float g_y[B_ * S_ * D_];        // attention output [B,S,D]

// ---------------------------------------------------------------------------
// TF32 GEMM: C[M,N] = A[M,K] @ W[K,N],  M = B_*S_ = 8192, K = D_ = 1024
// mode 0: scatter into g_q/g_k/g_v (N = 3*D_)
// mode 1: plain store to Cout (N = D_)
// Block tile 128x64, K-tile 32. 256 threads = 8 warps (4x2), warp tile 32x32.
// ---------------------------------------------------------------------------
#define BM 128
#define BN 64
#define BK 32
#define LDA 36   // BK + 4 pad
#define LDB 68   // BN + 4 pad
#define LDC 68

__global__ __launch_bounds__(256)
void gemm_tf32_kernel(const float* __restrict__ A_in,
                      const float* __restrict__ W,
                      float* __restrict__ Cout,
                      int N, int mode)
{
    const int K = D_;
    const float* A = A_in ? A_in : g_y;   // proj reads scratch

    // smem: phase1 As[128][36] + Bs[32][68]; phase2 Cs[128][68] (reuse)
    __shared__ __align__(16) char smem_raw[BM * LDC * 4];  // 34816 B (max phase)
    float* As = (float*)smem_raw;                  // 128*36*4 = 18432
    float* Bs = (float*)(smem_raw + BM * LDA * 4); // 32*68*4  = 8704
    float* Cs = (float*)smem_raw;

    const int tid = threadIdx.x;
    const int wid = tid >> 5;
    const int wm  = wid >> 1;   // 0..3  (rows of 32)
    const int wn  = wid & 1;    // 0..1  (cols of 32)
    const int m0  = blockIdx.y * BM;
    const int n0  = blockIdx.x * BN;

    wmma::fragment<wmma::accumulator, 16, 16, 8, float> c[2][2];
    #pragma unroll
    for (int i = 0; i < 2; i++)
        #pragma unroll
        for (int j = 0; j < 2; j++)
            wmma::fill_fragment(c[i][j], 0.0f);

    for (int k0 = 0; k0 < K; k0 += BK) {
        // Load A tile: 128x32 = 1024 float4, 4 per thread
        #pragma unroll
        for (int i = 0; i < 4; i++) {
            int idx = tid + i * 256;            // 0..1023
            int r   = idx >> 3;                 // 0..127
            int c4  = idx & 7;                  // 0..7
            float4 v = *(const float4*)(A + (size_t)(m0 + r) * K + k0 + c4 * 4);
            *(float4*)(As + r * LDA + c4 * 4) = v;
        }
        // Load W tile: 32x64 = 512 float4, 2 per thread
        #pragma unroll
        for (int i = 0; i < 2; i++) {
            int idx = tid + i * 256;            // 0..511
            int r   = idx >> 4;                 // 0..31
            int c4  = idx & 15;                 // 0..15
            float4 v = *(const float4*)(W + (size_t)(k0 + r) * N + n0 + c4 * 4);
            *(float4*)(Bs + r * LDB + c4 * 4) = v;
        }
        __syncthreads();

        #pragma unroll
        for (int kk = 0; kk < BK; kk += 8) {
            wmma::fragment<wmma::matrix_a, 16, 16, 8, wmma::precision::tf32, wmma::row_major> a[2];
            wmma::fragment<wmma::matrix_b, 16, 16, 8, wmma::precision::tf32, wmma::row_major> b[2];
            #pragma unroll
            for (int i = 0; i < 2; i++) {
                wmma::load_matrix_sync(a[i], As + (wm * 32 + i * 16) * LDA + kk, LDA);
                #pragma unroll
                for (int t = 0; t < a[i].num_elements; t++)
                    a[i].x[t] = wmma::__float_to_tf32(a[i].x[t]);
            }
            #pragma unroll
            for (int j = 0; j < 2; j++) {
                wmma::load_matrix_sync(b[j], Bs + kk * LDB + wn * 32 + j * 16, LDB);
                #pragma unroll
                for (int t = 0; t < b[j].num_elements; t++)
                    b[j].x[t] = wmma::__float_to_tf32(b[j].x[t]);
            }
            #pragma unroll
            for (int i = 0; i < 2; i++)
                #pragma unroll
                for (int j = 0; j < 2; j++)
                    wmma::mma_sync(c[i][j], a[i], b[j], c[i][j]);
        }
        __syncthreads();
    }

    // Epilogue: stage through smem, then (scatter-)store
    #pragma unroll
    for (int i = 0; i < 2; i++)
        #pragma unroll
        for (int j = 0; j < 2; j++)
            wmma::store_matrix_sync(Cs + (wm * 32 + i * 16) * LDC + wn * 32 + j * 16,
                                    c[i][j], LDC, wmma::mem_row_major);
    __syncthreads();

    #pragma unroll
    for (int e = 0; e < 32; e++) {
        int idx = tid + e * 256;     // 0..8191
        int r   = idx >> 6;          // 0..127
        int cc  = idx & 63;          // 0..63
        float val = Cs[r * LDC + cc];
        int row = m0 + r;
        int col = n0 + cc;
        if (mode == 0) {
            int part = col >> 10;        // 0=q 1=k 2=v
            int rem  = col & 1023;
            int h    = rem >> 6;
            int d    = rem & 63;
            int b    = row >> 11;        // / S_
            int s    = row & 2047;
            float* dst = (part == 0) ? g_q : ((part == 1) ? g_k : g_v);
            dst[(((size_t)(b * H_ + h)) * S_ + s) * HD + d] = val;
        } else {
            Cout[(size_t)row * N + col] = val;
        }
    }
}

// ---------------------------------------------------------------------------
// Causal flash attention. Q tile 64, K tile 32. grid = (S/64, B*H), 256 thr.
// Online softmax; QK^T and PV via TF32 wmma; O accumulated in smem.
// Static smem total = 8704+8704+9216+17408+512 = 44544 B (< 48 KB).
// ---------------------------------------------------------------------------
#define LDK 68   // Hd + 4
#define LDS 36   // 32 + 4
#define LDO 68

__global__ __launch_bounds__(256)
void attn_kernel()
{
    const int q0 = blockIdx.x * 64;
    const int bh = blockIdx.y;
    const int b  = bh >> 4;
    const int h  = bh & 15;

    const float* Qg = g_q + ((size_t)bh * S_ + q0) * HD;
    const float* Kg = g_k + (size_t)bh * S_ * HD;
    const float* Vg = g_v + (size_t)bh * S_ * HD;

    __shared__ __align__(16) float Ksh[32 * LDK];
    __shared__ __align__(16) float Vsh[32 * LDK];
    __shared__ __align__(16) float Ssh[64 * LDS];
    __shared__ __align__(16) float Osh[64 * LDO];
    __shared__ float m_sh[64];
    __shared__ float l_sh[64];

    const int tid = threadIdx.x;
    const int wid = tid >> 5;
    const int wm  = wid >> 1;   // 0..3 : q-row block of 16
    const int wn  = wid & 1;    // 0..1

    // Pre-load Q fragments (scaled by 1/sqrt(Hd) = 0.125), kept in registers
    wmma::fragment<wmma::matrix_a, 16, 16, 8, wmma::precision::tf32, wmma::row_major> qf[8];
    #pragma unroll
    for (int kk = 0; kk < 8; kk++) {
        wmma::load_matrix_sync(qf[kk], Qg + (size_t)(wm * 16) * HD + kk * 8, HD);
        #pragma unroll
        for (int t = 0; t < qf[kk].num_elements; t++)
            qf[kk].x[t] = wmma::__float_to_tf32(qf[kk].x[t] * 0.125f);
    }

    for (int i = tid; i < 64 * LDO; i += 256) Osh[i] = 0.0f;
    if (tid < 64) { m_sh[tid] = -1e30f; l_sh[tid] = 0.0f; }
    __syncthreads();

    const int njt = (q0 + 64) >> 5;   // causal: key tiles 0 .. (q0+63)/32
    for (int jt = 0; jt < njt; jt++) {
        const int j0 = jt * 32;

        // Load K,V tiles (32x64 each): 512 float4 per array, 2/thread
        #pragma unroll
        for (int i = 0; i < 2; i++) {
            int idx = tid + i * 256;
            int r   = idx >> 4;     // 0..31
            int c4  = idx & 15;     // 0..15
            *(float4*)(Ksh + r * LDK + c4 * 4) =
                *(const float4*)(Kg + (size_t)(j0 + r) * HD + c4 * 4);
            *(float4*)(Vsh + r * LDK + c4 * 4) =
                *(const float4*)(Vg + (size_t)(j0 + r) * HD + c4 * 4);
        }
        __syncthreads();

        // S = (Q*scale) @ K^T  -> each warp one 16x16 tile of the 64x32 S
        {
            wmma::fragment<wmma::accumulator, 16, 16, 8, float> sf;
            wmma::fill_fragment(sf, 0.0f);
            #pragma unroll
            for (int kk = 0; kk < 8; kk++) {
                wmma::fragment<wmma::matrix_b, 16, 16, 8, wmma::precision::tf32, wmma::col_major> bf;
                wmma::load_matrix_sync(bf, Ksh + (wn * 16) * LDK + kk * 8, LDK);
                #pragma unroll
                for (int t = 0; t < bf.num_elements; t++)
                    bf.x[t] = wmma::__float_to_tf32(bf.x[t]);
                wmma::mma_sync(sf, qf[kk], bf, sf);
            }
            wmma::store_matrix_sync(Ssh + (wm * 16) * LDS + wn * 16, sf, LDS, wmma::mem_row_major);
        }
        __syncthreads();

        // Online softmax update: 4 threads per row, 8 cols each
        {
            const int row  = tid >> 2;
            const int part = tid & 3;
            const int qg   = q0 + row;
            const int cb   = part * 8;

            float mval = -1e30f;
            #pragma unroll
            for (int cc = 0; cc < 8; cc++) {
                int col = cb + cc;
                float s = (j0 + col <= qg) ? Ssh[row * LDS + col] : -1e30f;
                mval = fmaxf(mval, s);
            }
            mval = fmaxf(mval, __shfl_xor_sync(0xffffffff, mval, 1));
            mval = fmaxf(mval, __shfl_xor_sync(0xffffffff, mval, 2));

            float mold = m_sh[row];
            float mnew = fmaxf(mold, mval);

            float psum = 0.0f;
            #pragma unroll
            for (int cc = 0; cc < 8; cc++) {
                int col = cb + cc;
                float s = (j0 + col <= qg) ? Ssh[row * LDS + col] : -1e30f;
                float p = __expf(s - mnew);
                Ssh[row * LDS + col] = p;
                psum += p;
            }
            psum += __shfl_xor_sync(0xffffffff, psum, 1);
            psum += __shfl_xor_sync(0xffffffff, psum, 2);

            float alpha = __expf(mold - mnew);
            #pragma unroll
            for (int cc = 0; cc < 16; cc++)
                Osh[row * LDO + part * 16 + cc] *= alpha;
            if (part == 0) {
                m_sh[row] = mnew;
                l_sh[row] = l_sh[row] * alpha + psum;
            }
        }
        __syncthreads();

        // O += P @ V : warp covers q block wm*16, d block wn*32 (2 frags)
        {
            wmma::fragment<wmma::accumulator, 16, 16, 8, float> of[2];
            #pragma unroll
            for (int j = 0; j < 2; j++)
                wmma::load_matrix_sync(of[j], Osh + (wm * 16) * LDO + wn * 32 + j * 16,
                                       LDO, wmma::mem_row_major);
            #pragma unroll
            for (int kk = 0; kk < 4; kk++) {
                wmma::fragment<wmma::matrix_a, 16, 16, 8, wmma::precision::tf32, wmma::row_major> pf;
                wmma::load_matrix_sync(pf, Ssh + (wm * 16) * LDS + kk * 8, LDS);
                #pragma unroll
                for (int t = 0; t < pf.num_elements; t++)
                    pf.x[t] = wmma::__float_to_tf32(pf.x[t]);
                #pragma unroll
                for (int j = 0; j < 2; j++) {
                    wmma::fragment<wmma::matrix_b, 16, 16, 8, wmma::precision::tf32, wmma::row_major> vf;
                    wmma::load_matrix_sync(vf, Vsh + (kk * 8) * LDK + wn * 32 + j * 16, LDK);
                    #pragma unroll
                    for (int t = 0; t < vf.num_elements; t++)
                        vf.x[t] = wmma::__float_to_tf32(vf.x[t]);
                    wmma::mma_sync(of[j], pf, vf, of[j]);
                }
            }
            #pragma unroll
            for (int j = 0; j < 2; j++)
                wmma::store_matrix_sync(Osh + (wm * 16) * LDO + wn * 32 + j * 16,
                                        of[j], LDO, wmma::mem_row_major);
        }
        __syncthreads();
    }

    // Normalize and write y [B,S,D] at column offset h*Hd
    {
        const int row  = tid >> 2;
        const int part = tid & 3;
        const float inv = 1.0f / l_sh[row];
        float* dst = g_y + ((size_t)(b * S_) + q0 + row) * D_ + h * HD;
        #pragma unroll
        for (int cc = 0; cc < 16; cc++) {
            int col = part * 16 + cc;
            dst[col] = Osh[row * LDO + col] * inv;
        }
    }
}

// ---------------------------------------------------------------------------
extern "C" void kernel_launch(void* const* d_in, const int* in_sizes, int n_in,
                              void* d_out, int out_size)
{
    const float* x      = (const float*)d_in[0];
    const float* w_qkv  = (const float*)d_in[1];
    const float* w_proj = (const float*)d_in[2];
    float* out          = (float*)d_out;

    dim3 blk(256);

    // 1) QKV GEMM + scatter into [B,H,S,Hd]
    gemm_tf32_kernel<<<dim3((3 * D_) / BN, (B_ * S_) / BM), blk>>>(
        x, w_qkv, nullptr, 3 * D_, 0);

    // 2) Causal flash attention
    attn_kernel<<<dim3(S_ / 64, B_ * H_), blk>>>();

    // 3) Output projection (A = g_y via nullptr sentinel)
    gemm_tf32_kernel<<<dim3(D_ / BN, (B_ * S_) / BM), blk>>>(
        nullptr, w_proj, out, D_, 1);
}

// round 4
// speedup vs baseline: 1.0784x; 1.0784x over previous
#include <cuda_runtime.h>
#include <cstdint>
#include <mma.h>

using namespace nvcuda;

#define B_  4
#define S_  2048
#define D_  1024
#define H_  16
#define HD  64

// Scratch (allocation-free per harness rules)
__device__ float g_q[B_ * H_ * S_ * HD];   // [B,H,S,Hd]
__device__ float g_k[B_ * H_ * S_ * HD];
__device__ float g_v[B_ * H_ * S_ * HD];
__device__ float g_y[B_ * S_ * D_];        // attention output [B,S,D]

// ---------------------------------------------------------------------------
// cp.async helpers
// ---------------------------------------------------------------------------
__device__ __forceinline__ void cpasync16(void* smem, const void* gmem) {
    unsigned s = (unsigned)__cvta_generic_to_shared(smem);
    asm volatile("cp.async.cg.shared.global [%0], [%1], 16;\n" :: "r"(s), "l"(gmem));
}
#define CP_COMMIT() asm volatile("cp.async.commit_group;\n" ::: "memory")
#define CP_WAIT0()  asm volatile("cp.async.wait_group 0;\n" ::: "memory")
#define CP_WAIT1()  asm volatile("cp.async.wait_group 1;\n" ::: "memory")

// ---------------------------------------------------------------------------
// TF32 GEMM: C[M,N] = A[M,K] @ W[K,N], K = 1024.
// Block tile 128x128, BK=16, double-buffered cp.async pipeline.
// 256 threads = 8 warps (4x2), warp tile 32x64 (2x4 accum frags).
// mode 0: scatter into g_q/g_k/g_v (N = 3072); mode 1: plain store (N = 1024).
// ---------------------------------------------------------------------------
#define BM 128
#define BN 128
#define BK 16
#define LDA 20    // 16 + 4
#define LDB 132   // 128 + 4
#define LDC 68

#define STAGE_BYTES (BM * LDA * 4 + BK * LDB * 4)   // 10240 + 8448 = 18688

__global__ __launch_bounds__(256)
void gemm_tf32_kernel(const float* __restrict__ A_in,
                      const float* __restrict__ W,
                      float* __restrict__ Cout,
                      int N, int mode)
{
    const int K = D_;
    const float* A = A_in ? A_in : g_y;

    __shared__ __align__(16) char smem_raw[2 * STAGE_BYTES];  // 37376 B
    float* As[2] = { (float*)smem_raw, (float*)(smem_raw + STAGE_BYTES) };
    float* Bs[2] = { (float*)(smem_raw + BM * LDA * 4),
                     (float*)(smem_raw + STAGE_BYTES + BM * LDA * 4) };
    float* Cs = (float*)smem_raw;   // 128 x 68 staging (34816 B), reused post-loop

    const int tid = threadIdx.x;
    const int wid = tid >> 5;
    const int wm  = wid >> 1;   // 0..3 (rows of 32)
    const int wn  = wid & 1;    // 0..1 (cols of 64)
    const int m0  = blockIdx.y * BM;
    const int n0  = blockIdx.x * BN;

    wmma::fragment<wmma::accumulator, 16, 16, 8, float> c[2][4];
    #pragma unroll
    for (int i = 0; i < 2; i++)
        #pragma unroll
        for (int j = 0; j < 4; j++)
            wmma::fill_fragment(c[i][j], 0.0f);

    auto issue = [&](int k0, int b) {
        // A tile: 128x16 = 512 float4, 2 per thread
        #pragma unroll
        for (int i = 0; i < 2; i++) {
            int idx = tid + i * 256;
            int r   = idx >> 2;     // 0..127
            int c4  = idx & 3;      // 0..3
            cpasync16(As[b] + r * LDA + c4 * 4,
                      A + (size_t)(m0 + r) * K + k0 + c4 * 4);
        }
        // W tile: 16x128 = 512 float4, 2 per thread
        #pragma unroll
        for (int i = 0; i < 2; i++) {
            int idx = tid + i * 256;
            int r   = idx >> 5;     // 0..15
            int c4  = idx & 31;     // 0..31
            cpasync16(Bs[b] + r * LDB + c4 * 4,
                      W + (size_t)(k0 + r) * N + n0 + c4 * 4);
        }
    };

    const int nIt = K / BK;    // 64
    issue(0, 0);
    CP_COMMIT();

    for (int it = 0; it < nIt; it++) {
        const int buf = it & 1;
        if (it + 1 < nIt) {
            issue((it + 1) * BK, buf ^ 1);
            CP_COMMIT();
            CP_WAIT1();
        } else {
            CP_WAIT0();
        }
        __syncthreads();

        #pragma unroll
        for (int kk = 0; kk < BK; kk += 8) {
            wmma::fragment<wmma::matrix_a, 16, 16, 8, wmma::precision::tf32, wmma::row_major> a[2];
            wmma::fragment<wmma::matrix_b, 16, 16, 8, wmma::precision::tf32, wmma::row_major> b[4];
            #pragma unroll
            for (int i = 0; i < 2; i++) {
                wmma::load_matrix_sync(a[i], As[buf] + (wm * 32 + i * 16) * LDA + kk, LDA);
                #pragma unroll
                for (int t = 0; t < a[i].num_elements; t++)
                    a[i].x[t] = wmma::__float_to_tf32(a[i].x[t]);
            }
            #pragma unroll
            for (int j = 0; j < 4; j++) {
                wmma::load_matrix_sync(b[j], Bs[buf] + kk * LDB + wn * 64 + j * 16, LDB);
                #pragma unroll
                for (int t = 0; t < b[j].num_elements; t++)
                    b[j].x[t] = wmma::__float_to_tf32(b[j].x[t]);
            }
            #pragma unroll
            for (int i = 0; i < 2; i++)
                #pragma unroll
                for (int j = 0; j < 4; j++)
                    wmma::mma_sync(c[i][j], a[i], b[j], c[i][j]);
        }
        __syncthreads();
    }

    // Epilogue in two 128x64 halves through Cs staging
    #pragma unroll
    for (int h = 0; h < 2; h++) {
        if (wn == h) {
            #pragma unroll
            for (int i = 0; i < 2; i++)
                #pragma unroll
                for (int j = 0; j < 4; j++)
                    wmma::store_matrix_sync(Cs + (wm * 32 + i * 16) * LDC + j * 16,
                                            c[i][j], LDC, wmma::mem_row_major);
        }
        __syncthreads();

        #pragma unroll
        for (int e = 0; e < 32; e++) {
            int idx = tid + e * 256;     // 0..8191
            int r   = idx >> 6;          // 0..127
            int cc  = idx & 63;          // 0..63
            float val = Cs[r * LDC + cc];
            int row = m0 + r;
            int col = n0 + h * 64 + cc;
            if (mode == 0) {
                int part = col >> 10;        // 0=q 1=k 2=v
                int rem  = col & 1023;
                int hh   = rem >> 6;
                int d    = rem & 63;
                int b    = row >> 11;
                int s    = row & 2047;
                float* dst = (part == 0) ? g_q : ((part == 1) ? g_k : g_v);
                dst[(((size_t)(b * H_ + hh)) * S_ + s) * HD + d] = val;
            } else {
                Cout[(size_t)row * N + col] = val;
            }
        }
        __syncthreads();
    }
}

// ---------------------------------------------------------------------------
// Causal flash attention. Q tile 64, K tile 32 (double-buffered cp.async).
// O accumulators live in registers (HMMA accum layout: row = (lane>>2) + 8*((e>>1)&1)).
// grid = (S/64, B*H), 256 threads.
// ---------------------------------------------------------------------------
#define LDK 68   // Hd + 4
#define LDS 36   // 32 + 4
#define LDO 68

__global__ __launch_bounds__(256)
void attn_kernel()
{
    const int q0 = blockIdx.x * 64;
    const int bh = blockIdx.y;
    const int b  = bh >> 4;
    const int h  = bh & 15;

    const float* Qg = g_q + ((size_t)bh * S_ + q0) * HD;
    const float* Kg = g_k + (size_t)bh * S_ * HD;
    const float* Vg = g_v + (size_t)bh * S_ * HD;

    __shared__ __align__(16) float Ksh[2][32 * LDK];
    __shared__ __align__(16) float Vsh[2][32 * LDK];
    __shared__ __align__(16) float Ssh[64 * LDS];
    __shared__ float m_sh[64];
    __shared__ float l_sh[64];
    __shared__ float a_sh[64];

    const int tid  = threadIdx.x;
    const int wid  = tid >> 5;
    const int lane = tid & 31;
    const int wm   = wid >> 1;   // 0..3 : q-row block of 16
    const int wn   = wid & 1;    // 0..1

    // Pre-load Q fragments (scaled by 1/sqrt(Hd) = 0.125)
    wmma::fragment<wmma::matrix_a, 16, 16, 8, wmma::precision::tf32, wmma::row_major> qf[8];
    #pragma unroll
    for (int kk = 0; kk < 8; kk++) {
        wmma::load_matrix_sync(qf[kk], Qg + (size_t)(wm * 16) * HD + kk * 8, HD);
        #pragma unroll
        for (int t = 0; t < qf[kk].num_elements; t++)
            qf[kk].x[t] = wmma::__float_to_tf32(qf[kk].x[t] * 0.125f);
    }

    // Register O accumulators: warp covers rows wm*16, cols wn*32 (+ j*16)
    wmma::fragment<wmma::accumulator, 16, 16, 8, float> of[2];
    wmma::fill_fragment(of[0], 0.0f);
    wmma::fill_fragment(of[1], 0.0f);

    if (tid < 64) { m_sh[tid] = -1e30f; l_sh[tid] = 0.0f; }

    auto issue_kv = [&](int j0, int bufi) {
        #pragma unroll
        for (int i = 0; i < 2; i++) {
            int idx = tid + i * 256;
            int r   = idx >> 4;     // 0..31
            int c4  = idx & 15;     // 0..15
            cpasync16(Ksh[bufi] + r * LDK + c4 * 4, Kg + (size_t)(j0 + r) * HD + c4 * 4);
            cpasync16(Vsh[bufi] + r * LDK + c4 * 4, Vg + (size_t)(j0 + r) * HD + c4 * 4);
        }
    };

    const int njt = (q0 + 64) >> 5;   // causal: key tiles 0 .. (q0+63)/32
    issue_kv(0, 0);
    CP_COMMIT();

    for (int jt = 0; jt < njt; jt++) {
        const int buf = jt & 1;
        const int j0  = jt * 32;
        if (jt + 1 < njt) {
            issue_kv((jt + 1) * 32, buf ^ 1);
            CP_COMMIT();
            CP_WAIT1();
        } else {
            CP_WAIT0();
        }
        __syncthreads();

        // S = (Q*scale) @ K^T : warp -> 16x16 tile at (wm*16, wn*16) of 64x32
        {
            wmma::fragment<wmma::accumulator, 16, 16, 8, float> sf;
            wmma::fill_fragment(sf, 0.0f);
            #pragma unroll
            for (int kk = 0; kk < 8; kk++) {
                wmma::fragment<wmma::matrix_b, 16, 16, 8, wmma::precision::tf32, wmma::col_major> bf;
                wmma::load_matrix_sync(bf, Ksh[buf] + (wn * 16) * LDK + kk * 8, LDK);
                #pragma unroll
                for (int t = 0; t < bf.num_elements; t++)
                    bf.x[t] = wmma::__float_to_tf32(bf.x[t]);
                wmma::mma_sync(sf, qf[kk], bf, sf);
            }
            wmma::store_matrix_sync(Ssh + (wm * 16) * LDS + wn * 16, sf, LDS, wmma::mem_row_major);
        }
        __syncthreads();

        // Online softmax (smem pass, layout-safe): 4 threads/row, 8 cols each
        {
            const int row  = tid >> 2;
            const int part = tid & 3;
            const int qg   = q0 + row;
            const int cb   = part * 8;

            float mval = -1e30f;
            #pragma unroll
            for (int cc = 0; cc < 8; cc++) {
                int col = cb + cc;
                float s = (j0 + col <= qg) ? Ssh[row * LDS + col] : -1e30f;
                mval = fmaxf(mval, s);
            }
            mval = fmaxf(mval, __shfl_xor_sync(0xffffffff, mval, 1));
            mval = fmaxf(mval, __shfl_xor_sync(0xffffffff, mval, 2));

            float mold = m_sh[row];
            float mnew = fmaxf(mold, mval);

            float psum = 0.0f;
            #pragma unroll
            for (int cc = 0; cc < 8; cc++) {
                int col = cb + cc;
                float s = (j0 + col <= qg) ? Ssh[row * LDS + col] : -1e30f;
                float p = __expf(s - mnew);
                Ssh[row * LDS + col] = p;
                psum += p;
            }
            psum += __shfl_xor_sync(0xffffffff, psum, 1);
            psum += __shfl_xor_sync(0xffffffff, psum, 2);

            if (part == 0) {
                float alpha = __expf(mold - mnew);
                m_sh[row] = mnew;
                l_sh[row] = l_sh[row] * alpha + psum;
                a_sh[row] = alpha;
            }
        }
        __syncthreads();

        // Rescale register O by per-row alpha (accumulator layout row map),
        // then O += P @ V
        {
            const float alo = a_sh[wm * 16 + (lane >> 2)];
            const float ahi = a_sh[wm * 16 + (lane >> 2) + 8];
            #pragma unroll
            for (int j = 0; j < 2; j++)
                #pragma unroll
                for (int e = 0; e < 8; e++)
                    of[j].x[e] *= ((e >> 1) & 1) ? ahi : alo;

            #pragma unroll
            for (int kk = 0; kk < 4; kk++) {
                wmma::fragment<wmma::matrix_a, 16, 16, 8, wmma::precision::tf32, wmma::row_major> pf;
                wmma::load_matrix_sync(pf, Ssh + (wm * 16) * LDS + kk * 8, LDS);
                #pragma unroll
                for (int t = 0; t < pf.num_elements; t++)
                    pf.x[t] = wmma::__float_to_tf32(pf.x[t]);
                #pragma unroll
                for (int j = 0; j < 2; j++) {
                    wmma::fragment<wmma::matrix_b, 16, 16, 8, wmma::precision::tf32, wmma::row_major> vf;
                    wmma::load_matrix_sync(vf, Vsh[buf] + (kk * 8) * LDK + wn * 32 + j * 16, LDK);
                    #pragma unroll
                    for (int t = 0; t < vf.num_elements; t++)
                        vf.x[t] = wmma::__float_to_tf32(vf.x[t]);
                    wmma::mma_sync(of[j], pf, vf, of[j]);
                }
            }
        }
        __syncthreads();
    }

    // Stage O through smem (reuse Ksh[0..1] = 64x68 floats), normalize, write
    {
        float* stage = &Ksh[0][0];   // 2*32*68 = 4352 floats = 64*68
        #pragma unroll
        for (int j = 0; j < 2; j++)
            wmma::store_matrix_sync(stage + (wm * 16) * LDO + wn * 32 + j * 16,
                                    of[j], LDO, wmma::mem_row_major);
        __syncthreads();

        const int row  = tid >> 2;
        const int part = tid & 3;
        const float inv = 1.0f / l_sh[row];
        float* dst = g_y + ((size_t)(b * S_) + q0 + row) * D_ + h * HD;
        #pragma unroll
        for (int cc = 0; cc < 16; cc++) {
            int col = part * 16 + cc;
            dst[col] = stage[row * LDO + col] * inv;
        }
    }
}

// ---------------------------------------------------------------------------
extern "C" void kernel_launch(void* const* d_in, const int* in_sizes, int n_in,
                              void* d_out, int out_size)
{
    const float* x      = (const float*)d_in[0];
    const float* w_qkv  = (const float*)d_in[1];
    const float* w_proj = (const float*)d_in[2];
    float* out          = (float*)d_out;

    dim3 blk(256);

    // 1) QKV GEMM + scatter into [B,H,S,Hd]
    gemm_tf32_kernel<<<dim3((3 * D_) / BN, (B_ * S_) / BM), blk>>>(
        x, w_qkv, nullptr, 3 * D_, 0);

    // 2) Causal flash attention
    attn_kernel<<<dim3(S_ / 64, B_ * H_), blk>>>();

    // 3) Output projection (A = g_y via nullptr sentinel)
    gemm_tf32_kernel<<<dim3(D_ / BN, (B_ * S_) / BM), blk>>>(
        nullptr, w_proj, out, D_, 1);
}

// round 5
// speedup vs baseline: 1.1907x; 1.1041x over previous
#include <cuda_runtime.h>
#include <cstdint>
#include <mma.h>

using namespace nvcuda;

#define B_  4
#define S_  2048
#define D_  1024
#define H_  16
#define HD  64

// Scratch (allocation-free per harness rules)
__device__ float g_q[B_ * H_ * S_ * HD];   // [B,H,S,Hd]  (TF32-rounded)
__device__ float g_k[B_ * H_ * S_ * HD];
__device__ float g_v[B_ * H_ * S_ * HD];
__device__ float g_y[B_ * S_ * D_];        // attention out [B,S,D] (TF32-rounded)
__device__ float g_xr[B_ * S_ * D_];       // TF32-rounded x
__device__ float g_wqkvr[D_ * 3 * D_];     // TF32-rounded w_qkv
__device__ float g_wprojr[D_ * D_];        // TF32-rounded w_proj

// ---------------------------------------------------------------------------
__device__ __forceinline__ float tf32r(float x) { return wmma::__float_to_tf32(x); }

__global__ __launch_bounds__(256)
void round_kernel(const float* __restrict__ in, float* __restrict__ out, int n4)
{
    int i = blockIdx.x * blockDim.x + threadIdx.x;
    if (i < n4) {
        float4 v = ((const float4*)in)[i];
        v.x = tf32r(v.x); v.y = tf32r(v.y); v.z = tf32r(v.z); v.w = tf32r(v.w);
        ((float4*)out)[i] = v;
    }
}

// ---------------------------------------------------------------------------
// cp.async helpers
// ---------------------------------------------------------------------------
__device__ __forceinline__ void cpasync16(void* smem, const void* gmem) {
    unsigned s = (unsigned)__cvta_generic_to_shared(smem);
    asm volatile("cp.async.cg.shared.global [%0], [%1], 16;\n" :: "r"(s), "l"(gmem));
}
#define CP_COMMIT() asm volatile("cp.async.commit_group;\n" ::: "memory")
#define CP_WAIT0()  asm volatile("cp.async.wait_group 0;\n" ::: "memory")
#define CP_WAIT1()  asm volatile("cp.async.wait_group 1;\n" ::: "memory")

// ---------------------------------------------------------------------------
// TF32 GEMM: C[M,N] = A[M,K] @ W[K,N], K = 1024. Inputs PRE-ROUNDED to TF32,
// so the mainloop has NO cvt instructions.
// Block tile 128x128, BK=16, double-buffered cp.async. 8 warps, 32x64 warp tile.
// mode 0: scatter into g_q/g_k/g_v, rounding to TF32 (N = 3072)
// mode 1: plain fp32 store (N = 1024)
// ---------------------------------------------------------------------------
#define BM 128
#define BN 128
#define BK 16
#define LDA 20    // 16 + 4
#define LDB 132   // 128 + 4
#define LDC 68

#define STAGE_BYTES (BM * LDA * 4 + BK * LDB * 4)   // 18688

__global__ __launch_bounds__(256, 2)
void gemm_tf32_kernel(const float* __restrict__ A,
                      const float* __restrict__ W,
                      float* __restrict__ Cout,
                      int N, int mode)
{
    const int K = D_;

    __shared__ __align__(16) char smem_raw[2 * STAGE_BYTES];  // 37376 B
    float* As[2] = { (float*)smem_raw, (float*)(smem_raw + STAGE_BYTES) };
    float* Bs[2] = { (float*)(smem_raw + BM * LDA * 4),
                     (float*)(smem_raw + STAGE_BYTES + BM * LDA * 4) };
    float* Cs = (float*)smem_raw;   // 128x68 staging, reused post-loop

    const int tid = threadIdx.x;
    const int wid = tid >> 5;
    const int wm  = wid >> 1;   // 0..3 (rows of 32)
    const int wn  = wid & 1;    // 0..1 (cols of 64)
    const int m0  = blockIdx.y * BM;
    const int n0  = blockIdx.x * BN;

    wmma::fragment<wmma::accumulator, 16, 16, 8, float> c[2][4];
    #pragma unroll
    for (int i = 0; i < 2; i++)
        #pragma unroll
        for (int j = 0; j < 4; j++)
            wmma::fill_fragment(c[i][j], 0.0f);

    auto issue = [&](int k0, int b) {
        #pragma unroll
        for (int i = 0; i < 2; i++) {
            int idx = tid + i * 256;
            int r   = idx >> 2;     // 0..127
            int c4  = idx & 3;      // 0..3
            cpasync16(As[b] + r * LDA + c4 * 4,
                      A + (size_t)(m0 + r) * K + k0 + c4 * 4);
        }
        #pragma unroll
        for (int i = 0; i < 2; i++) {
            int idx = tid + i * 256;
            int r   = idx >> 5;     // 0..15
            int c4  = idx & 31;     // 0..31
            cpasync16(Bs[b] + r * LDB + c4 * 4,
                      W + (size_t)(k0 + r) * N + n0 + c4 * 4);
        }
    };

    const int nIt = K / BK;    // 64
    issue(0, 0);
    CP_COMMIT();

    for (int it = 0; it < nIt; it++) {
        const int buf = it & 1;
        if (it + 1 < nIt) {
            issue((it + 1) * BK, buf ^ 1);
            CP_COMMIT();
            CP_WAIT1();
        } else {
            CP_WAIT0();
        }
        __syncthreads();

        #pragma unroll
        for (int kk = 0; kk < BK; kk += 8) {
            wmma::fragment<wmma::matrix_a, 16, 16, 8, wmma::precision::tf32, wmma::row_major> a[2];
            wmma::fragment<wmma::matrix_b, 16, 16, 8, wmma::precision::tf32, wmma::row_major> b[4];
            #pragma unroll
            for (int i = 0; i < 2; i++)
                wmma::load_matrix_sync(a[i], As[buf] + (wm * 32 + i * 16) * LDA + kk, LDA);
            #pragma unroll
            for (int j = 0; j < 4; j++)
                wmma::load_matrix_sync(b[j], Bs[buf] + kk * LDB + wn * 64 + j * 16, LDB);
            #pragma unroll
            for (int i = 0; i < 2; i++)
                #pragma unroll
                for (int j = 0; j < 4; j++)
                    wmma::mma_sync(c[i][j], a[i], b[j], c[i][j]);
        }
        __syncthreads();
    }

    // Epilogue in two 128x64 halves through Cs staging
    #pragma unroll
    for (int h = 0; h < 2; h++) {
        if (wn == h) {
            #pragma unroll
            for (int i = 0; i < 2; i++)
                #pragma unroll
                for (int j = 0; j < 4; j++)
                    wmma::store_matrix_sync(Cs + (wm * 32 + i * 16) * LDC + j * 16,
                                            c[i][j], LDC, wmma::mem_row_major);
        }
        __syncthreads();

        #pragma unroll
        for (int e = 0; e < 32; e++) {
            int idx = tid + e * 256;     // 0..8191
            int r   = idx >> 6;          // 0..127
            int cc  = idx & 63;          // 0..63
            float val = Cs[r * LDC + cc];
            int row = m0 + r;
            int col = n0 + h * 64 + cc;
            if (mode == 0) {
                int part = col >> 10;        // 0=q 1=k 2=v
                int rem  = col & 1023;
                int hh   = rem >> 6;
                int d    = rem & 63;
                int b    = row >> 11;
                int s    = row & 2047;
                float* dst = (part == 0) ? g_q : ((part == 1) ? g_k : g_v);
                // round once here; attention then needs no per-use cvt
                dst[(((size_t)(b * H_ + hh)) * S_ + s) * HD + d] = tf32r(val);
            } else {
                Cout[(size_t)row * N + col] = val;
            }
        }
        __syncthreads();
    }
}

// ---------------------------------------------------------------------------
// Causal flash attention. Q tile 64, K tile 32 (double-buffered cp.async).
// Q/K/V pre-rounded to TF32 -> no cvts except on softmax P.
// O accumulators in registers (accum row map: row=(lane>>2)+8*((e>>1)&1)).
// ---------------------------------------------------------------------------
#define LDK 68   // Hd + 4
#define LDS 36   // 32 + 4
#define LDO 68

__global__ __launch_bounds__(256, 2)
void attn_kernel()
{
    const int q0 = blockIdx.x * 64;
    const int bh = blockIdx.y;
    const int b  = bh >> 4;
    const int h  = bh & 15;

    const float* Qg = g_q + ((size_t)bh * S_ + q0) * HD;
    const float* Kg = g_k + (size_t)bh * S_ * HD;
    const float* Vg = g_v + (size_t)bh * S_ * HD;

    __shared__ __align__(16) float Ksh[2][32 * LDK];
    __shared__ __align__(16) float Vsh[2][32 * LDK];
    __shared__ __align__(16) float Ssh[64 * LDS];
    __shared__ float m_sh[64];
    __shared__ float l_sh[64];
    __shared__ float a_sh[64];

    const int tid  = threadIdx.x;
    const int wid  = tid >> 5;
    const int lane = tid & 31;
    const int wm   = wid >> 1;   // 0..3 : q-row block of 16
    const int wn   = wid & 1;    // 0..1

    // Q fragments: pre-rounded; x0.125 is a power of two -> stays exact TF32
    wmma::fragment<wmma::matrix_a, 16, 16, 8, wmma::precision::tf32, wmma::row_major> qf[8];
    #pragma unroll
    for (int kk = 0; kk < 8; kk++) {
        wmma::load_matrix_sync(qf[kk], Qg + (size_t)(wm * 16) * HD + kk * 8, HD);
        #pragma unroll
        for (int t = 0; t < qf[kk].num_elements; t++)
            qf[kk].x[t] = qf[kk].x[t] * 0.125f;
    }

    wmma::fragment<wmma::accumulator, 16, 16, 8, float> of[2];
    wmma::fill_fragment(of[0], 0.0f);
    wmma::fill_fragment(of[1], 0.0f);

    if (tid < 64) { m_sh[tid] = -1e30f; l_sh[tid] = 0.0f; }

    auto issue_kv = [&](int j0, int bufi) {
        #pragma unroll
        for (int i = 0; i < 2; i++) {
            int idx = tid + i * 256;
            int r   = idx >> 4;     // 0..31
            int c4  = idx & 15;     // 0..15
            cpasync16(Ksh[bufi] + r * LDK + c4 * 4, Kg + (size_t)(j0 + r) * HD + c4 * 4);
            cpasync16(Vsh[bufi] + r * LDK + c4 * 4, Vg + (size_t)(j0 + r) * HD + c4 * 4);
        }
    };

    const int njt = (q0 + 64) >> 5;
    issue_kv(0, 0);
    CP_COMMIT();

    for (int jt = 0; jt < njt; jt++) {
        const int buf = jt & 1;
        const int j0  = jt * 32;
        if (jt + 1 < njt) {
            issue_kv((jt + 1) * 32, buf ^ 1);
            CP_COMMIT();
            CP_WAIT1();
        } else {
            CP_WAIT0();
        }
        __syncthreads();

        // S = (Q*scale) @ K^T : warp -> 16x16 tile at (wm*16, wn*16)
        {
            wmma::fragment<wmma::accumulator, 16, 16, 8, float> sf;
            wmma::fill_fragment(sf, 0.0f);
            #pragma unroll
            for (int kk = 0; kk < 8; kk++) {
                wmma::fragment<wmma::matrix_b, 16, 16, 8, wmma::precision::tf32, wmma::col_major> bf;
                wmma::load_matrix_sync(bf, Ksh[buf] + (wn * 16) * LDK + kk * 8, LDK);
                wmma::mma_sync(sf, qf[kk], bf, sf);
            }
            wmma::store_matrix_sync(Ssh + (wm * 16) * LDS + wn * 16, sf, LDS, wmma::mem_row_major);
        }
        __syncthreads();

        // Online softmax: 4 threads/row, 8 cols each
        {
            const int row  = tid >> 2;
            const int part = tid & 3;
            const int qg   = q0 + row;
            const int cb   = part * 8;

            float mval = -1e30f;
            #pragma unroll
            for (int cc = 0; cc < 8; cc++) {
                int col = cb + cc;
                float s = (j0 + col <= qg) ? Ssh[row * LDS + col] : -1e30f;
                mval = fmaxf(mval, s);
            }
            mval = fmaxf(mval, __shfl_xor_sync(0xffffffff, mval, 1));
            mval = fmaxf(mval, __shfl_xor_sync(0xffffffff, mval, 2));

            float mold = m_sh[row];
            float mnew = fmaxf(mold, mval);

            float psum = 0.0f;
            #pragma unroll
            for (int cc = 0; cc < 8; cc++) {
                int col = cb + cc;
                float s = (j0 + col <= qg) ? Ssh[row * LDS + col] : -1e30f;
                float p = __expf(s - mnew);
                Ssh[row * LDS + col] = tf32r(p);   // round P once at write
                psum += p;
            }
            psum += __shfl_xor_sync(0xffffffff, psum, 1);
            psum += __shfl_xor_sync(0xffffffff, psum, 2);

            if (part == 0) {
                float alpha = __expf(mold - mnew);
                m_sh[row] = mnew;
                l_sh[row] = l_sh[row] * alpha + psum;
                a_sh[row] = alpha;
            }
        }
        __syncthreads();

        // Rescale register O by per-row alpha, then O += P @ V
        {
            const float alo = a_sh[wm * 16 + (lane >> 2)];
            const float ahi = a_sh[wm * 16 + (lane >> 2) + 8];
            #pragma unroll
            for (int j = 0; j < 2; j++)
                #pragma unroll
                for (int e = 0; e < 8; e++)
                    of[j].x[e] *= ((e >> 1) & 1) ? ahi : alo;

            #pragma unroll
            for (int kk = 0; kk < 4; kk++) {
                wmma::fragment<wmma::matrix_a, 16, 16, 8, wmma::precision::tf32, wmma::row_major> pf;
                wmma::load_matrix_sync(pf, Ssh + (wm * 16) * LDS + kk * 8, LDS);
                #pragma unroll
                for (int j = 0; j < 2; j++) {
                    wmma::fragment<wmma::matrix_b, 16, 16, 8, wmma::precision::tf32, wmma::row_major> vf;
                    wmma::load_matrix_sync(vf, Vsh[buf] + (kk * 8) * LDK + wn * 32 + j * 16, LDK);
                    wmma::mma_sync(of[j], pf, vf, of[j]);
                }
            }
        }
        __syncthreads();
    }

    // Stage O through smem, normalize, round to TF32 (feeds proj GEMM), write
    {
        float* stage = &Ksh[0][0];   // 64*68 floats
        #pragma unroll
        for (int j = 0; j < 2; j++)
            wmma::store_matrix_sync(stage + (wm * 16) * LDO + wn * 32 + j * 16,
                                    of[j], LDO, wmma::mem_row_major);
        __syncthreads();

        const int row  = tid >> 2;
        const int part = tid & 3;
        const float inv = 1.0f / l_sh[row];
        float* dst = g_y + ((size_t)(b * S_) + q0 + row) * D_ + h * HD;
        #pragma unroll
        for (int cc = 0; cc < 16; cc++) {
            int col = part * 16 + cc;
            dst[col] = tf32r(stage[row * LDO + col] * inv);
        }
    }
}

// ---------------------------------------------------------------------------
extern "C" void kernel_launch(void* const* d_in, const int* in_sizes, int n_in,
                              void* d_out, int out_size)
{
    const float* x      = (const float*)d_in[0];
    const float* w_qkv  = (const float*)d_in[1];
    const float* w_proj = (const float*)d_in[2];
    float* out          = (float*)d_out;

    float *xr, *wq, *wp, *yr;
    cudaGetSymbolAddress((void**)&xr, g_xr);
    cudaGetSymbolAddress((void**)&wq, g_wqkvr);
    cudaGetSymbolAddress((void**)&wp, g_wprojr);
    cudaGetSymbolAddress((void**)&yr, g_y);

    dim3 blk(256);

    // 0) One-time TF32 rounding passes (removes all mainloop cvts)
    round_kernel<<<(B_ * S_ * D_ / 4 + 255) / 256, blk>>>(x, xr, B_ * S_ * D_ / 4);
    round_kernel<<<(D_ * 3 * D_ / 4 + 255) / 256, blk>>>(w_qkv, wq, D_ * 3 * D_ / 4);
    round_kernel<<<(D_ * D_ / 4 + 255) / 256, blk>>>(w_proj, wp, D_ * D_ / 4);

    // 1) QKV GEMM + scatter (rounds Q/K/V at write)
    gemm_tf32_kernel<<<dim3((3 * D_) / BN, (B_ * S_) / BM), blk>>>(
        xr, wq, nullptr, 3 * D_, 0);

    // 2) Causal flash attention (rounds y at write)
    attn_kernel<<<dim3(S_ / 64, B_ * H_), blk>>>();

    // 3) Output projection
    gemm_tf32_kernel<<<dim3(D_ / BN, (B_ * S_) / BM), blk>>>(
        yr, wp, out, D_, 1);
}

// round 7
// speedup vs baseline: 1.1998x; 1.0076x over previous
#include <cuda_runtime.h>
#include <cstdint>
#include <mma.h>

using namespace nvcuda;

#define B_  4
#define S_  2048
#define D_  1024
#define H_  16
#define HD  64

// Scratch (allocation-free per harness rules)
__device__ float g_q[B_ * H_ * S_ * HD];   // [B,H,S,Hd]  (TF32-rounded)
__device__ float g_k[B_ * H_ * S_ * HD];
__device__ float g_v[B_ * H_ * S_ * HD];
__device__ float g_y[B_ * S_ * D_];        // attention out [B,S,D] (TF32-rounded)
__device__ float g_xr[B_ * S_ * D_];       // TF32-rounded x
__device__ float g_wqkvr[D_ * 3 * D_];     // TF32-rounded w_qkv
__device__ float g_wprojr[D_ * D_];        // TF32-rounded w_proj

// ---------------------------------------------------------------------------
__device__ __forceinline__ float tf32r(float x) { return wmma::__float_to_tf32(x); }

__global__ __launch_bounds__(256)
void round_kernel(const float* __restrict__ in, float* __restrict__ out, int n4)
{
    int i = blockIdx.x * blockDim.x + threadIdx.x;
    if (i < n4) {
        float4 v = ((const float4*)in)[i];
        v.x = tf32r(v.x); v.y = tf32r(v.y); v.z = tf32r(v.z); v.w = tf32r(v.w);
        ((float4*)out)[i] = v;
    }
}

// ---------------------------------------------------------------------------
// cp.async helpers
// ---------------------------------------------------------------------------
__device__ __forceinline__ void cpasync16(void* smem, const void* gmem) {
    unsigned s = (unsigned)__cvta_generic_to_shared(smem);
    asm volatile("cp.async.cg.shared.global [%0], [%1], 16;\n" :: "r"(s), "l"(gmem));
}
#define CP_COMMIT() asm volatile("cp.async.commit_group;\n" ::: "memory")
#define CP_WAIT0()  asm volatile("cp.async.wait_group 0;\n" ::: "memory")
#define CP_WAIT1()  asm volatile("cp.async.wait_group 1;\n" ::: "memory")

// ---------------------------------------------------------------------------
// TF32 GEMM: C[M,N] = A[M,K] @ W[K,N], K = 1024. Inputs pre-rounded to TF32.
// Block tile 128x128, BK=16, double-buffered cp.async.
// 128 threads = 4 warps (2x2), warp tile 64x64 (4x4 accum frags)
//   -> 16 HMMA per 32 LDS-elt fragment loads per kk step (2x better than r5).
// mode 0: scatter into g_q/g_k/g_v with TF32 rounding (N = 3072)
// mode 1: plain fp32 store (N = 1024)
// ---------------------------------------------------------------------------
#define BM 128
#define BN 128
#define BK 16
#define LDA 20    // 16 + 4
#define LDB 132   // 128 + 4
#define LDC 68

#define STAGE_BYTES (BM * LDA * 4 + BK * LDB * 4)   // 18688

__global__ __launch_bounds__(128, 2)
void gemm_tf32_kernel(const float* __restrict__ A,
                      const float* __restrict__ W,
                      float* __restrict__ Cout,
                      int N, int mode)
{
    const int K = D_;

    __shared__ __align__(16) char smem_raw[2 * STAGE_BYTES];  // 37376 B
    float* As[2] = { (float*)smem_raw, (float*)(smem_raw + STAGE_BYTES) };
    float* Bs[2] = { (float*)(smem_raw + BM * LDA * 4),
                     (float*)(smem_raw + STAGE_BYTES + BM * LDA * 4) };
    float* Cs = (float*)smem_raw;   // 128x68 staging (34816 B), reused post-loop

    const int tid = threadIdx.x;    // 0..127
    const int wid = tid >> 5;       // 0..3
    const int wm  = wid >> 1;       // 0..1 (row block of 64)
    const int wn  = wid & 1;        // 0..1 (col block of 64)
    const int m0  = blockIdx.y * BM;
    const int n0  = blockIdx.x * BN;

    wmma::fragment<wmma::accumulator, 16, 16, 8, float> c[4][4];
    #pragma unroll
    for (int i = 0; i < 4; i++)
        #pragma unroll
        for (int j = 0; j < 4; j++)
            wmma::fill_fragment(c[i][j], 0.0f);

    auto issue = [&](int k0, int b) {
        // A tile: 128x16 = 512 float4, 4 per thread
        #pragma unroll
        for (int i = 0; i < 4; i++) {
            int idx = tid + i * 128;
            int r   = idx >> 2;     // 0..127
            int c4  = idx & 3;      // 0..3
            cpasync16(As[b] + r * LDA + c4 * 4,
                      A + (size_t)(m0 + r) * K + k0 + c4 * 4);
        }
        // W tile: 16x128 = 512 float4, 4 per thread
        #pragma unroll
        for (int i = 0; i < 4; i++) {
            int idx = tid + i * 128;
            int r   = idx >> 5;     // 0..15
            int c4  = idx & 31;     // 0..31
            cpasync16(Bs[b] + r * LDB + c4 * 4,
                      W + (size_t)(k0 + r) * N + n0 + c4 * 4);
        }
    };

    const int nIt = K / BK;    // 64
    issue(0, 0);
    CP_COMMIT();

    for (int it = 0; it < nIt; it++) {
        const int buf = it & 1;
        if (it + 1 < nIt) {
            issue((it + 1) * BK, buf ^ 1);
            CP_COMMIT();
            CP_WAIT1();
        } else {
            CP_WAIT0();
        }
        __syncthreads();

        #pragma unroll
        for (int kk = 0; kk < BK; kk += 8) {
            wmma::fragment<wmma::matrix_a, 16, 16, 8, wmma::precision::tf32, wmma::row_major> a[4];
            wmma::fragment<wmma::matrix_b, 16, 16, 8, wmma::precision::tf32, wmma::row_major> b[4];
            #pragma unroll
            for (int i = 0; i < 4; i++)
                wmma::load_matrix_sync(a[i], As[buf] + (wm * 64 + i * 16) * LDA + kk, LDA);
            #pragma unroll
            for (int j = 0; j < 4; j++)
                wmma::load_matrix_sync(b[j], Bs[buf] + kk * LDB + wn * 64 + j * 16, LDB);
            #pragma unroll
            for (int i = 0; i < 4; i++)
                #pragma unroll
                for (int j = 0; j < 4; j++)
                    wmma::mma_sync(c[i][j], a[i], b[j], c[i][j]);
        }
        __syncthreads();
    }

    // Epilogue in two 128x64 halves through Cs staging
    #pragma unroll
    for (int h = 0; h < 2; h++) {
        if (wn == h) {
            #pragma unroll
            for (int i = 0; i < 4; i++)
                #pragma unroll
                for (int j = 0; j < 4; j++)
                    wmma::store_matrix_sync(Cs + (wm * 64 + i * 16) * LDC + j * 16,
                                            c[i][j], LDC, wmma::mem_row_major);
        }
        __syncthreads();

        #pragma unroll
        for (int e = 0; e < 64; e++) {
            int idx = tid + e * 128;     // 0..8191
            int r   = idx >> 6;          // 0..127
            int cc  = idx & 63;          // 0..63
            float val = Cs[r * LDC + cc];
            int row = m0 + r;
            int col = n0 + h * 64 + cc;
            if (mode == 0) {
                int part = col >> 10;        // 0=q 1=k 2=v
                int rem  = col & 1023;
                int hh   = rem >> 6;
                int d    = rem & 63;
                int b    = row >> 11;
                int s    = row & 2047;
                float* dst = (part == 0) ? g_q : ((part == 1) ? g_k : g_v);
                dst[(((size_t)(b * H_ + hh)) * S_ + s) * HD + d] = tf32r(val);
            } else {
                Cout[(size_t)row * N + col] = val;
            }
        }
        __syncthreads();
    }
}

// ---------------------------------------------------------------------------
// Causal flash attention. Q tile 64, K tile 64 (double-buffered cp.async,
// dynamic smem 87.8 KB, 2 CTA/SM). 256 threads = 8 warps (4x2):
// warp (wm,wn): q rows wm*16, cols wn*32.
// O accumulators in registers (accum row map: row=(lane>>2)+8*((e>>1)&1)).
// ---------------------------------------------------------------------------
#define KT  64        // key tile
#define LDK 68        // Hd + 4
#define LDS2 68       // KT + 4

// dynamic smem layout (floats):
//  K: 2 * KT * LDK = 8704   | V: 8704 | S: 64*LDS2 = 4352 | m,l,a: 192
#define ATTN_K_OFF   0
#define ATTN_V_OFF   (2 * KT * LDK)
#define ATTN_S_OFF   (ATTN_V_OFF + 2 * KT * LDK)
#define ATTN_M_OFF   (ATTN_S_OFF + 64 * LDS2)
#define ATTN_L_OFF   (ATTN_M_OFF + 64)
#define ATTN_A_OFF   (ATTN_L_OFF + 64)
#define ATTN_FLOATS  (ATTN_A_OFF + 64)
#define ATTN_SMEM_BYTES (ATTN_FLOATS * 4)   // 87808

__global__ __launch_bounds__(256, 2)
void attn_kernel()
{
    extern __shared__ __align__(16) float dsm[];
    float* Kbuf = dsm + ATTN_K_OFF;   // [2][KT*LDK]
    float* Vbuf = dsm + ATTN_V_OFF;
    float* Ssh  = dsm + ATTN_S_OFF;   // 64 x LDS2
    float* m_sh = dsm + ATTN_M_OFF;
    float* l_sh = dsm + ATTN_L_OFF;
    float* a_sh = dsm + ATTN_A_OFF;

    const int q0 = blockIdx.x * 64;
    const int bh = blockIdx.y;
    const int b  = bh >> 4;
    const int h  = bh & 15;

    const float* Qg = g_q + ((size_t)bh * S_ + q0) * HD;
    const float* Kg = g_k + (size_t)bh * S_ * HD;
    const float* Vg = g_v + (size_t)bh * S_ * HD;

    const int tid  = threadIdx.x;
    const int wid  = tid >> 5;
    const int lane = tid & 31;
    const int wm   = wid >> 1;   // 0..3 : q-row block of 16
    const int wn   = wid & 1;    // 0..1 : col block of 32

    // Q fragments: pre-rounded TF32; x0.125 power-of-two stays exact
    wmma::fragment<wmma::matrix_a, 16, 16, 8, wmma::precision::tf32, wmma::row_major> qf[8];
    #pragma unroll
    for (int kk = 0; kk < 8; kk++) {
        wmma::load_matrix_sync(qf[kk], Qg + (size_t)(wm * 16) * HD + kk * 8, HD);
        #pragma unroll
        for (int t = 0; t < qf[kk].num_elements; t++)
            qf[kk].x[t] = qf[kk].x[t] * 0.125f;
    }

    wmma::fragment<wmma::accumulator, 16, 16, 8, float> of[2];
    wmma::fill_fragment(of[0], 0.0f);
    wmma::fill_fragment(of[1], 0.0f);

    if (tid < 64) { m_sh[tid] = -1e30f; l_sh[tid] = 0.0f; }

    auto issue_kv = [&](int j0, int bufi) {
        float* Kd = Kbuf + bufi * (KT * LDK);
        float* Vd = Vbuf + bufi * (KT * LDK);
        #pragma unroll
        for (int i = 0; i < 4; i++) {
            int idx = tid + i * 256;    // 0..1023
            int r   = idx >> 4;         // 0..63
            int c4  = idx & 15;         // 0..15
            cpasync16(Kd + r * LDK + c4 * 4, Kg + (size_t)(j0 + r) * HD + c4 * 4);
            cpasync16(Vd + r * LDK + c4 * 4, Vg + (size_t)(j0 + r) * HD + c4 * 4);
        }
    };

    const int njt = blockIdx.x + 1;    // causal: tiles 0..q0/64
    issue_kv(0, 0);
    CP_COMMIT();

    for (int jt = 0; jt < njt; jt++) {
        const int buf = jt & 1;
        const int j0  = jt * KT;
        if (jt + 1 < njt) {
            issue_kv((jt + 1) * KT, buf ^ 1);
            CP_COMMIT();
            CP_WAIT1();
        } else {
            CP_WAIT0();
        }
        __syncthreads();

        const float* Ksh = Kbuf + buf * (KT * LDK);
        const float* Vsh = Vbuf + buf * (KT * LDK);

        // S = (Q*scale) @ K^T : warp -> rows wm*16, cols wn*32 (2 frags)
        {
            wmma::fragment<wmma::accumulator, 16, 16, 8, float> sf[2];
            wmma::fill_fragment(sf[0], 0.0f);
            wmma::fill_fragment(sf[1], 0.0f);
            #pragma unroll
            for (int kk = 0; kk < 8; kk++) {
                #pragma unroll
                for (int j = 0; j < 2; j++) {
                    wmma::fragment<wmma::matrix_b, 16, 16, 8, wmma::precision::tf32, wmma::col_major> bf;
                    wmma::load_matrix_sync(bf, Ksh + (wn * 32 + j * 16) * LDK + kk * 8, LDK);
                    wmma::mma_sync(sf[j], qf[kk], bf, sf[j]);
                }
            }
            #pragma unroll
            for (int j = 0; j < 2; j++)
                wmma::store_matrix_sync(Ssh + (wm * 16) * LDS2 + wn * 32 + j * 16,
                                        sf[j], LDS2, wmma::mem_row_major);
        }
        __syncthreads();

        // Online softmax: 4 threads/row, 16 cols each
        {
            const int row  = tid >> 2;
            const int part = tid & 3;
            const int qg   = q0 + row;
            const int cb   = part * 16;

            float mval = -1e30f;
            #pragma unroll
            for (int cc = 0; cc < 16; cc++) {
                int col = cb + cc;
                float s = (j0 + col <= qg) ? Ssh[row * LDS2 + col] : -1e30f;
                mval = fmaxf(mval, s);
            }
            mval = fmaxf(mval, __shfl_xor_sync(0xffffffff, mval, 1));
            mval = fmaxf(mval, __shfl_xor_sync(0xffffffff, mval, 2));

            float mold = m_sh[row];
            float mnew = fmaxf(mold, mval);

            float psum = 0.0f;
            #pragma unroll
            for (int cc = 0; cc < 16; cc++) {
                int col = cb + cc;
                float s = (j0 + col <= qg) ? Ssh[row * LDS2 + col] : -1e30f;
                float p = __expf(s - mnew);
                Ssh[row * LDS2 + col] = tf32r(p);
                psum += p;
            }
            psum += __shfl_xor_sync(0xffffffff, psum, 1);
            psum += __shfl_xor_sync(0xffffffff, psum, 2);

            if (part == 0) {
                float alpha = __expf(mold - mnew);
                m_sh[row] = mnew;
                l_sh[row] = l_sh[row] * alpha + psum;
                a_sh[row] = alpha;
            }
        }
        __syncthreads();

        // Rescale register O by per-row alpha, then O += P @ V
        {
            const float alo = a_sh[wm * 16 + (lane >> 2)];
            const float ahi = a_sh[wm * 16 + (lane >> 2) + 8];
            #pragma unroll
            for (int j = 0; j < 2; j++)
                #pragma unroll
                for (int e = 0; e < 8; e++)
                    of[j].x[e] *= ((e >> 1) & 1) ? ahi : alo;

            #pragma unroll
            for (int kk = 0; kk < 8; kk++) {
                wmma::fragment<wmma::matrix_a, 16, 16, 8, wmma::precision::tf32, wmma::row_major> pf;
                wmma::load_matrix_sync(pf, Ssh + (wm * 16) * LDS2 + kk * 8, LDS2);
                #pragma unroll
                for (int j = 0; j < 2; j++) {
                    wmma::fragment<wmma::matrix_b, 16, 16, 8, wmma::precision::tf32, wmma::row_major> vf;
                    wmma::load_matrix_sync(vf, Vsh + (kk * 8) * LDK + wn * 32 + j * 16, LDK);
                    wmma::mma_sync(of[j], pf, vf, of[j]);
                }
            }
        }
        __syncthreads();
    }

    // Stage O through smem (reuse K region), normalize, write
    {
        float* stage = Kbuf;    // 64 x LDK floats is enough (64*68)
        #pragma unroll
        for (int j = 0; j < 2; j++)
            wmma::store_matrix_sync(stage + (wm * 16) * LDK + wn * 32 + j * 16,
                                    of[j], LDK, wmma::mem_row_major);
        __syncthreads();

        const int row  = tid >> 2;
        const int part = tid & 3;
        const float inv = 1.0f / l_sh[row];
        float* dst = g_y + ((size_t)(b * S_) + q0 + row) * D_ + h * HD;
        #pragma unroll
        for (int cc = 0; cc < 16; cc++) {
            int col = part * 16 + cc;
            dst[col] = tf32r(stage[row * LDK + col] * inv);
        }
    }
}

// ---------------------------------------------------------------------------
extern "C" void kernel_launch(void* const* d_in, const int* in_sizes, int n_in,
                              void* d_out, int out_size)
{
    const float* x      = (const float*)d_in[0];
    const float* w_qkv  = (const float*)d_in[1];
    const float* w_proj = (const float*)d_in[2];
    float* out          = (float*)d_out;

    float *xr, *wq, *wp, *yr;
    cudaGetSymbolAddress((void**)&xr, g_xr);
    cudaGetSymbolAddress((void**)&wq, g_wqkvr);
    cudaGetSymbolAddress((void**)&wp, g_wprojr);
    cudaGetSymbolAddress((void**)&yr, g_y);

    cudaFuncSetAttribute(attn_kernel,
                         cudaFuncAttributeMaxDynamicSharedMemorySize,
                         ATTN_SMEM_BYTES);

    // 0) One-time TF32 rounding passes (no mainloop cvts anywhere)
    round_kernel<<<(B_ * S_ * D_ / 4 + 255) / 256, 256>>>(x, xr, B_ * S_ * D_ / 4);
    round_kernel<<<(D_ * 3 * D_ / 4 + 255) / 256, 256>>>(w_qkv, wq, D_ * 3 * D_ / 4);
    round_kernel<<<(D_ * D_ / 4 + 255) / 256, 256>>>(w_proj, wp, D_ * D_ / 4);

    // 1) QKV GEMM + scatter (rounds Q/K/V at write)
    gemm_tf32_kernel<<<dim3((3 * D_) / BN, (B_ * S_) / BM), 128>>>(
        xr, wq, nullptr, 3 * D_, 0);

    // 2) Causal flash attention (rounds y at write)
    attn_kernel<<<dim3(S_ / 64, B_ * H_), 256, ATTN_SMEM_BYTES>>>();

    // 3) Output projection
    gemm_tf32_kernel<<<dim3(D_ / BN, (B_ * S_) / BM), 128>>>(
        yr, wp, out, D_, 1);
}

// round 9
// speedup vs baseline: 1.3193x; 1.0996x over previous
#include <cuda_runtime.h>
#include <cstdint>
#include <mma.h>

using namespace nvcuda;

#define B_  4
#define S_  2048
#define D_  1024
#define H_  16
#define HD  64
#define M_TOT (B_ * S_)

// Scratch (allocation-free per harness rules)
__device__ float g_q[B_ * H_ * S_ * HD];   // [B,H,S,Hd]  tf32-rounded
__device__ float g_k[B_ * H_ * S_ * HD];
__device__ float g_v[B_ * H_ * S_ * HD];
__device__ float g_y[M_TOT * D_];          // attention out (tf32-rounded)
__device__ float g_xr[M_TOT * D_];         // tf32-rounded x
__device__ float g_wqkvr[D_ * 3 * D_];     // tf32-rounded w_qkv
__device__ float g_wprojr[D_ * D_];        // tf32-rounded w_proj

__device__ __forceinline__ float tf32r(float x) { return wmma::__float_to_tf32(x); }

__global__ __launch_bounds__(256)
void round_kernel(const float* __restrict__ in, float* __restrict__ out, int n4)
{
    int i = blockIdx.x * blockDim.x + threadIdx.x;
    if (i < n4) {
        float4 v = ((const float4*)in)[i];
        v.x = tf32r(v.x); v.y = tf32r(v.y); v.z = tf32r(v.z); v.w = tf32r(v.w);
        ((float4*)out)[i] = v;
    }
}

// ---------------------------------------------------------------------------
// cp.async helpers
// ---------------------------------------------------------------------------
__device__ __forceinline__ void cpasync16(void* smem, const void* gmem) {
    unsigned s = (unsigned)__cvta_generic_to_shared(smem);
    asm volatile("cp.async.cg.shared.global [%0], [%1], 16;\n" :: "r"(s), "l"(gmem));
}
#define CP_COMMIT() asm volatile("cp.async.commit_group;\n" ::: "memory")
#define CP_WAIT0()  asm volatile("cp.async.wait_group 0;\n" ::: "memory")
#define CP_WAIT1()  asm volatile("cp.async.wait_group 1;\n" ::: "memory")

// ---------------------------------------------------------------------------
// TF32 GEMM: C[M,N] = A[M,K] @ W[K,N], K=1024, inputs pre-rounded to TF32.
// Block tile 128x128, BK=16, THREE-stage cp.async pipeline (dynamic smem).
// 256 threads = 8 warps (4x2), warp tile 32x64.
// mode 0: scatter g_q/g_k/g_v (tf32-rounded); mode 1: plain store.
// ---------------------------------------------------------------------------
#define BM 128
#define BN 128
#define BK 16
#define LDA 20
#define LDB 132
#define LDC 68
#define G_STAGE_B (BM * LDA * 4 + BK * LDB * 4)   // 18688
#define G_SMEM_B  (3 * G_STAGE_B)                  // 56064

__global__ __launch_bounds__(256, 2)
void gemm_tf32_kernel(const float* __restrict__ A,
                      const float* __restrict__ W,
                      float* __restrict__ Cout,
                      int N, int mode)
{
    extern __shared__ __align__(16) char gsm[];
    const int K = D_;

    const int tid = threadIdx.x;
    const int wid = tid >> 5;
    const int wm  = wid >> 1;   // 0..3
    const int wn  = wid & 1;    // 0..1
    const int m0  = blockIdx.y * BM;
    const int n0  = blockIdx.x * BN;

    wmma::fragment<wmma::accumulator, 16, 16, 8, float> c[2][4];
    #pragma unroll
    for (int i = 0; i < 2; i++)
        #pragma unroll
        for (int j = 0; j < 4; j++)
            wmma::fill_fragment(c[i][j], 0.0f);

    auto issue = [&](int it, int s) {
        float* As = (float*)(gsm + s * G_STAGE_B);
        float* Bs = As + BM * LDA;
        int k0 = it * BK;
        #pragma unroll
        for (int i = 0; i < 2; i++) {
            int idx = tid + i * 256;
            int r   = idx >> 2;
            int c4  = idx & 3;
            cpasync16(As + r * LDA + c4 * 4, A + (size_t)(m0 + r) * K + k0 + c4 * 4);
        }
        #pragma unroll
        for (int i = 0; i < 2; i++) {
            int idx = tid + i * 256;
            int r   = idx >> 5;
            int c4  = idx & 31;
            cpasync16(Bs + r * LDB + c4 * 4, W + (size_t)(k0 + r) * N + n0 + c4 * 4);
        }
        CP_COMMIT();
    };

    const int nIt = K / BK;    // 64
    issue(0, 0);
    issue(1, 1);

    for (int it = 0; it < nIt; it++) {
        const int s = it % 3;
        if (it + 1 < nIt) CP_WAIT1(); else CP_WAIT0();
        __syncthreads();

        float* As = (float*)(gsm + s * G_STAGE_B);
        float* Bs = As + BM * LDA;
        #pragma unroll
        for (int kk = 0; kk < BK; kk += 8) {
            wmma::fragment<wmma::matrix_a, 16, 16, 8, wmma::precision::tf32, wmma::row_major> a[2];
            wmma::fragment<wmma::matrix_b, 16, 16, 8, wmma::precision::tf32, wmma::row_major> b[4];
            #pragma unroll
            for (int i = 0; i < 2; i++)
                wmma::load_matrix_sync(a[i], As + (wm * 32 + i * 16) * LDA + kk, LDA);
            #pragma unroll
            for (int j = 0; j < 4; j++)
                wmma::load_matrix_sync(b[j], Bs + kk * LDB + wn * 64 + j * 16, LDB);
            #pragma unroll
            for (int i = 0; i < 2; i++)
                #pragma unroll
                for (int j = 0; j < 4; j++)
                    wmma::mma_sync(c[i][j], a[i], b[j], c[i][j]);
        }
        if (it + 2 < nIt) issue(it + 2, (it + 2) % 3);
    }
    __syncthreads();

    // Epilogue: two 128x64 halves through smem staging (reuses pipeline smem)
    float* Cs = (float*)gsm;
    #pragma unroll
    for (int h = 0; h < 2; h++) {
        if (wn == h) {
            #pragma unroll
            for (int i = 0; i < 2; i++)
                #pragma unroll
                for (int j = 0; j < 4; j++)
                    wmma::store_matrix_sync(Cs + (wm * 32 + i * 16) * LDC + j * 16,
                                            c[i][j], LDC, wmma::mem_row_major);
        }
        __syncthreads();

        #pragma unroll
        for (int e = 0; e < 32; e++) {
            int idx = tid + e * 256;
            int r   = idx >> 6;
            int cc  = idx & 63;
            float val = Cs[r * LDC + cc];
            int row = m0 + r;
            int col = n0 + h * 64 + cc;
            if (mode == 0) {
                int part = col >> 10;
                int rem  = col & 1023;
                int hh   = rem >> 6;
                int d    = rem & 63;
                int bb   = row >> 11;
                int ss   = row & 2047;
                float* dst = (part == 0) ? g_q : ((part == 1) ? g_k : g_v);
                dst[(((size_t)(bb * H_ + hh)) * S_ + ss) * HD + d] = tf32r(val);
            } else {
                Cout[(size_t)row * N + col] = val;
            }
        }
        __syncthreads();
    }
}

// ---------------------------------------------------------------------------
// Causal flash attention, FA2-style. Q tile 128, K tile 64, 256 threads =
// 8 warps; warp w owns q rows [w*16, w*16+16) x all 64 key cols.
// Softmax fully in registers (warp-local); P staged in per-warp smem slice.
// Accumulator map: row=(lane>>2)+8*((e>>1)&1); col=(lane&3)*2+(e&1)+8*(e>>2).
// ---------------------------------------------------------------------------
#define KT   64
#define LDK  68
// dynamic smem floats: K 2*64*68 | V 2*64*68 | P 8*16*68
#define AK_OFF 0
#define AV_OFF (2 * KT * LDK)
#define AP_OFF (4 * KT * LDK)
#define A_FLOATS (AP_OFF + 8 * 16 * LDK)
#define A_SMEM_B (A_FLOATS * 4)    // 104448

__global__ __launch_bounds__(256, 2)
void attn_kernel()
{
    extern __shared__ __align__(16) float dsm[];
    float* Kbuf = dsm + AK_OFF;
    float* Vbuf = dsm + AV_OFF;

    const int q0 = blockIdx.x * 128;
    const int bh = blockIdx.y;
    const int b  = bh >> 4;
    const int h  = bh & 15;

    const float* Qg = g_q + ((size_t)bh * S_ + q0) * HD;
    const float* Kg = g_k + (size_t)bh * S_ * HD;
    const float* Vg = g_v + (size_t)bh * S_ * HD;

    const int tid  = threadIdx.x;
    const int wm   = tid >> 5;       // warp 0..7 -> q rows wm*16
    const int lane = tid & 31;
    float* Pw = dsm + AP_OFF + wm * (16 * LDK);   // per-warp 16x68 slice

    const int qbase  = q0 + wm * 16 + (lane >> 2);  // row for "lo" half
    const int c_base = (lane & 3) * 2;

    // Q fragments (pre-rounded tf32; x0.125 exact)
    wmma::fragment<wmma::matrix_a, 16, 16, 8, wmma::precision::tf32, wmma::row_major> qf[8];
    #pragma unroll
    for (int kk = 0; kk < 8; kk++) {
        wmma::load_matrix_sync(qf[kk], Qg + (size_t)(wm * 16) * HD + kk * 8, HD);
        #pragma unroll
        for (int t = 0; t < qf[kk].num_elements; t++)
            qf[kk].x[t] = qf[kk].x[t] * 0.125f;
    }

    wmma::fragment<wmma::accumulator, 16, 16, 8, float> of[4];
    #pragma unroll
    for (int j = 0; j < 4; j++) wmma::fill_fragment(of[j], 0.0f);

    float m_st[2] = { -1e30f, -1e30f };
    float l_st[2] = { 0.0f, 0.0f };

    auto issue_kv = [&](int j0, int bufi) {
        float* Kd = Kbuf + bufi * (KT * LDK);
        float* Vd = Vbuf + bufi * (KT * LDK);
        #pragma unroll
        for (int i = 0; i < 4; i++) {
            int idx = tid + i * 256;
            int r   = idx >> 4;
            int c4  = idx & 15;
            cpasync16(Kd + r * LDK + c4 * 4, Kg + (size_t)(j0 + r) * HD + c4 * 4);
            cpasync16(Vd + r * LDK + c4 * 4, Vg + (size_t)(j0 + r) * HD + c4 * 4);
        }
    };

    const int njt = 2 * blockIdx.x + 2;   // causal: key tiles cover cols <= q0+127
    issue_kv(0, 0);
    CP_COMMIT();

    for (int jt = 0; jt < njt; jt++) {
        const int buf = jt & 1;
        const int j0  = jt * KT;
        if (jt + 1 < njt) {
            issue_kv((jt + 1) * KT, buf ^ 1);
            CP_COMMIT();
            CP_WAIT1();
        } else {
            CP_WAIT0();
        }
        __syncthreads();

        const float* Ksh = Kbuf + buf * (KT * LDK);
        const float* Vsh = Vbuf + buf * (KT * LDK);

        // S = (Q*scale) @ K^T : 16x64 per warp, 4 accum frags in regs
        wmma::fragment<wmma::accumulator, 16, 16, 8, float> sf[4];
        #pragma unroll
        for (int j = 0; j < 4; j++) wmma::fill_fragment(sf[j], 0.0f);
        #pragma unroll
        for (int kk = 0; kk < 8; kk++) {
            #pragma unroll
            for (int j = 0; j < 4; j++) {
                wmma::fragment<wmma::matrix_b, 16, 16, 8, wmma::precision::tf32, wmma::col_major> bf;
                wmma::load_matrix_sync(bf, Ksh + (j * 16) * LDK + kk * 8, LDK);
                wmma::mma_sync(sf[j], qf[kk], bf, sf[j]);
            }
        }

        // Causal mask + online softmax, fully in registers
        float mx[2] = { -1e30f, -1e30f };
        #pragma unroll
        for (int j = 0; j < 4; j++) {
            #pragma unroll
            for (int e = 0; e < 8; e++) {
                int col = j0 + j * 16 + c_base + (e & 1) + 8 * ((e >> 2) & 1);
                int hv  = (e >> 1) & 1;
                int row = qbase + 8 * hv;
                if (col > row) sf[j].x[e] = -1e30f;
                mx[hv] = fmaxf(mx[hv], sf[j].x[e]);
            }
        }
        #pragma unroll
        for (int hv = 0; hv < 2; hv++) {
            mx[hv] = fmaxf(mx[hv], __shfl_xor_sync(0xffffffff, mx[hv], 1));
            mx[hv] = fmaxf(mx[hv], __shfl_xor_sync(0xffffffff, mx[hv], 2));
        }
        float mn[2] = { fmaxf(m_st[0], mx[0]), fmaxf(m_st[1], mx[1]) };
        float al[2] = { __expf(m_st[0] - mn[0]), __expf(m_st[1] - mn[1]) };

        float ps[2] = { 0.0f, 0.0f };
        #pragma unroll
        for (int j = 0; j < 4; j++) {
            #pragma unroll
            for (int e = 0; e < 8; e++) {
                int hv = (e >> 1) & 1;
                float p = __expf(sf[j].x[e] - mn[hv]);
                ps[hv] += p;
                sf[j].x[e] = tf32r(p);
            }
        }
        #pragma unroll
        for (int hv = 0; hv < 2; hv++) {
            ps[hv] += __shfl_xor_sync(0xffffffff, ps[hv], 1);
            ps[hv] += __shfl_xor_sync(0xffffffff, ps[hv], 2);
            l_st[hv] = l_st[hv] * al[hv] + ps[hv];
            m_st[hv] = mn[hv];
        }

        // Rescale O, stage P (warp-private), then O += P @ V
        #pragma unroll
        for (int j = 0; j < 4; j++)
            #pragma unroll
            for (int e = 0; e < 8; e++)
                of[j].x[e] *= al[(e >> 1) & 1];

        #pragma unroll
        for (int j = 0; j < 4; j++)
            wmma::store_matrix_sync(Pw + j * 16, sf[j], LDK, wmma::mem_row_major);
        __syncwarp();

        #pragma unroll
        for (int kk = 0; kk < 8; kk++) {
            wmma::fragment<wmma::matrix_a, 16, 16, 8, wmma::precision::tf32, wmma::row_major> pf;
            wmma::load_matrix_sync(pf, Pw + kk * 8, LDK);
            #pragma unroll
            for (int j = 0; j < 4; j++) {
                wmma::fragment<wmma::matrix_b, 16, 16, 8, wmma::precision::tf32, wmma::row_major> vf;
                wmma::load_matrix_sync(vf, Vsh + (kk * 8) * LDK + j * 16, LDK);
                wmma::mma_sync(of[j], pf, vf, of[j]);
            }
        }
        __syncthreads();   // protect K/V buffer reuse by next iteration's issue
    }

    // Epilogue: per-warp stage O + 1/l, normalize, tf32-round, write g_y
    {
        if ((lane & 3) == 0) {
            Pw[(lane >> 2) * LDK + 64]       = 1.0f / l_st[0];
            Pw[((lane >> 2) + 8) * LDK + 64] = 1.0f / l_st[1];
        }
        #pragma unroll
        for (int j = 0; j < 4; j++)
            wmma::store_matrix_sync(Pw + j * 16, of[j], LDK, wmma::mem_row_major);
        __syncwarp();

        #pragma unroll
        for (int e = 0; e < 32; e++) {
            int idx = lane + e * 32;        // 0..1023
            int r   = idx >> 6;             // 0..15
            int cc  = idx & 63;
            float v = Pw[r * LDK + cc] * Pw[r * LDK + 64];
            int row = q0 + wm * 16 + r;
            g_y[((size_t)(b * S_) + row) * D_ + h * HD + cc] = tf32r(v);
        }
    }
}

// ---------------------------------------------------------------------------
extern "C" void kernel_launch(void* const* d_in, const int* in_sizes, int n_in,
                              void* d_out, int out_size)
{
    const float* x      = (const float*)d_in[0];
    const float* w_qkv  = (const float*)d_in[1];
    const float* w_proj = (const float*)d_in[2];
    float* out          = (float*)d_out;

    float *xr, *wq, *wp, *yr;
    cudaGetSymbolAddress((void**)&xr, g_xr);
    cudaGetSymbolAddress((void**)&wq, g_wqkvr);
    cudaGetSymbolAddress((void**)&wp, g_wprojr);
    cudaGetSymbolAddress((void**)&yr, g_y);

    cudaFuncSetAttribute(gemm_tf32_kernel,
                         cudaFuncAttributeMaxDynamicSharedMemorySize, G_SMEM_B);
    cudaFuncSetAttribute(attn_kernel,
                         cudaFuncAttributeMaxDynamicSharedMemorySize, A_SMEM_B);

    // 0) One-time TF32 rounding passes
    round_kernel<<<(M_TOT * D_ / 4 + 255) / 256, 256>>>(x, xr, M_TOT * D_ / 4);
    round_kernel<<<(D_ * 3 * D_ / 4 + 255) / 256, 256>>>(w_qkv, wq, D_ * 3 * D_ / 4);
    round_kernel<<<(D_ * D_ / 4 + 255) / 256, 256>>>(w_proj, wp, D_ * D_ / 4);

    // 1) QKV GEMM + scatter
    gemm_tf32_kernel<<<dim3(3 * D_ / BN, M_TOT / BM), 256, G_SMEM_B>>>(
        xr, wq, nullptr, 3 * D_, 0);

    // 2) Causal flash attention (Q tile 128)
    attn_kernel<<<dim3(S_ / 128, B_ * H_), 256, A_SMEM_B>>>();

    // 3) Output projection
    gemm_tf32_kernel<<<dim3(D_ / BN, M_TOT / BM), 256, G_SMEM_B>>>(
        yr, wp, out, D_, 1);
}

// round 10
// speedup vs baseline: 1.9316x; 1.4641x over previous
#include <cuda_runtime.h>
#include <cstdint>
#include <mma.h>

using namespace nvcuda;

#define B_  4
#define S_  2048
#define D_  1024
#define H_  16
#define HD  64
#define M_TOT (B_ * S_)

// Scratch (allocation-free per harness rules)
__device__ float g_q[B_ * H_ * S_ * HD];   // [B,H,S,Hd]  tf32-rounded
__device__ float g_k[B_ * H_ * S_ * HD];
__device__ float g_v[B_ * H_ * S_ * HD];
__device__ float g_y[M_TOT * D_];          // attention out (tf32-rounded)
__device__ float g_xr[M_TOT * D_];         // tf32-rounded x       [M][K]
__device__ float g_wqkvt[3 * D_ * D_];     // tf32-rounded w_qkv^T [N=3072][K]
__device__ float g_wprojt[D_ * D_];        // tf32-rounded w_proj^T[N=1024][K]

__device__ __forceinline__ float tf32r(float x) { return wmma::__float_to_tf32(x); }

__global__ __launch_bounds__(256)
void round_kernel(const float* __restrict__ in, float* __restrict__ out, int n4)
{
    int i = blockIdx.x * blockDim.x + threadIdx.x;
    if (i < n4) {
        float4 v = ((const float4*)in)[i];
        v.x = tf32r(v.x); v.y = tf32r(v.y); v.z = tf32r(v.z); v.w = tf32r(v.w);
        ((float4*)out)[i] = v;
    }
}

// in [K][N] fp32 -> out [N][K] tf32-rounded (tiled transpose)
__global__ __launch_bounds__(256)
void tround_kernel(const float* __restrict__ in, float* __restrict__ out,
                   int K, int N)
{
    __shared__ float t[32][33];
    const int n0 = blockIdx.x * 32;
    const int k0 = blockIdx.y * 32;
    const int tx = threadIdx.x, ty = threadIdx.y;   // 32 x 8
    #pragma unroll
    for (int i = 0; i < 4; i++)
        t[ty + i * 8][tx] = in[(size_t)(k0 + ty + i * 8) * N + n0 + tx];
    __syncthreads();
    #pragma unroll
    for (int i = 0; i < 4; i++)
        out[(size_t)(n0 + ty + i * 8) * K + k0 + tx] = tf32r(t[tx][ty + i * 8]);
}

// ---------------------------------------------------------------------------
// cp.async helpers
// ---------------------------------------------------------------------------
__device__ __forceinline__ void cpasync16(void* smem, const void* gmem) {
    unsigned s = (unsigned)__cvta_generic_to_shared(smem);
    asm volatile("cp.async.cg.shared.global [%0], [%1], 16;\n" :: "r"(s), "l"(gmem));
}
#define CP_COMMIT() asm volatile("cp.async.commit_group;\n" ::: "memory")
#define CP_WAIT0()  asm volatile("cp.async.wait_group 0;\n" ::: "memory")
#define CP_WAIT1()  asm volatile("cp.async.wait_group 1;\n" ::: "memory")

__device__ __forceinline__ void ldsm_x4(uint32_t addr, uint32_t& r0, uint32_t& r1,
                                        uint32_t& r2, uint32_t& r3) {
    asm volatile("ldmatrix.sync.aligned.m8n8.x4.shared.b16 {%0,%1,%2,%3}, [%4];"
                 : "=r"(r0), "=r"(r1), "=r"(r2), "=r"(r3) : "r"(addr));
}

__device__ __forceinline__ void mma_tf32(float& d0, float& d1, float& d2, float& d3,
                                         uint32_t a0, uint32_t a1, uint32_t a2, uint32_t a3,
                                         uint32_t b0, uint32_t b1) {
    asm volatile(
        "mma.sync.aligned.m16n8k8.row.col.f32.tf32.tf32.f32 "
        "{%0,%1,%2,%3}, {%4,%5,%6,%7}, {%8,%9}, {%0,%1,%2,%3};"
        : "+f"(d0), "+f"(d1), "+f"(d2), "+f"(d3)
        : "r"(a0), "r"(a1), "r"(a2), "r"(a3), "r"(b0), "r"(b1));
}

// ---------------------------------------------------------------------------
// TF32 GEMM via ldmatrix + raw mma: C[M,N] = A[M,K] @ Wt[N,K]^T, K=1024.
// A row-major [M][K]; W pre-transposed to [N][K]. Inputs pre-rounded TF32.
// Block tile 128x128, BK=16, 3-stage cp.async. 256 thr = 8 warps (4x2),
// warp tile 32x64. Per k8: 2 A-LDSM.x4 + 4 B-LDSM.x4 + 16 mma.m16n8k8.
// mode 0: scatter g_q/g_k/g_v (tf32-rounded); mode 1: plain store.
// ---------------------------------------------------------------------------
#define BM 128
#define BN 128
#define BK 16
#define LDA 20
#define LDB 20
#define LDC 68
#define G_STAGE_F (BM * LDA + BN * LDB)            // 5120 floats
#define G_STAGE_B (G_STAGE_F * 4)                  // 20480
#define G_SMEM_B  (3 * G_STAGE_B)                  // 61440

__global__ __launch_bounds__(256, 2)
void gemm_tf32_kernel(const float* __restrict__ A,
                      const float* __restrict__ Wt,
                      float* __restrict__ Cout,
                      int N, int mode)
{
    extern __shared__ __align__(16) char gsm[];
    const uint32_t smem_base = (uint32_t)__cvta_generic_to_shared(gsm);
    const int K = D_;

    const int tid  = threadIdx.x;
    const int wid  = tid >> 5;
    const int lane = tid & 31;
    const int wm   = wid >> 1;   // 0..3 (rows of 32)
    const int wn   = wid & 1;    // 0..1 (cols of 64)
    const int m0   = blockIdx.y * BM;
    const int n0   = blockIdx.x * BN;

    // ldmatrix per-thread offsets (floats)
    const int a_row = (lane & 7) + 8 * ((lane >> 3) & 1);
    const int a_k   = 4 * ((lane >> 4) & 1);
    const int b_row = (lane & 7) + 8 * ((lane >> 4) & 1);
    const int b_k   = 4 * ((lane >> 3) & 1);
    int aoff[2], boff[4];
    #pragma unroll
    for (int mi = 0; mi < 2; mi++)
        aoff[mi] = (wm * 32 + mi * 16 + a_row) * LDA + a_k;
    #pragma unroll
    for (int ni = 0; ni < 4; ni++)
        boff[ni] = BM * LDA + (wn * 64 + ni * 16 + b_row) * LDB + b_k;

    float c[2][8][4];
    #pragma unroll
    for (int mi = 0; mi < 2; mi++)
        #pragma unroll
        for (int nj = 0; nj < 8; nj++)
            #pragma unroll
            for (int e = 0; e < 4; e++)
                c[mi][nj][e] = 0.0f;

    auto issue = [&](int it, int s) {
        float* As = (float*)(gsm + s * G_STAGE_B);
        float* Bs = As + BM * LDA;
        int k0 = it * BK;
        #pragma unroll
        for (int i = 0; i < 2; i++) {
            int idx = tid + i * 256;
            int r   = idx >> 2;
            int c4  = idx & 3;
            cpasync16(As + r * LDA + c4 * 4, A  + (size_t)(m0 + r) * K + k0 + c4 * 4);
        }
        #pragma unroll
        for (int i = 0; i < 2; i++) {
            int idx = tid + i * 256;
            int r   = idx >> 2;
            int c4  = idx & 3;
            cpasync16(Bs + r * LDB + c4 * 4, Wt + (size_t)(n0 + r) * K + k0 + c4 * 4);
        }
        CP_COMMIT();
    };

    const int nIt = K / BK;    // 64
    issue(0, 0);
    issue(1, 1);

    for (int it = 0; it < nIt; it++) {
        const int s = it % 3;
        if (it + 1 < nIt) CP_WAIT1(); else CP_WAIT0();
        __syncthreads();

        const uint32_t st = smem_base + s * G_STAGE_B;
        #pragma unroll
        for (int kk = 0; kk < BK; kk += 8) {
            uint32_t a[2][4], b[4][4];
            #pragma unroll
            for (int mi = 0; mi < 2; mi++)
                ldsm_x4(st + (aoff[mi] + kk) * 4, a[mi][0], a[mi][1], a[mi][2], a[mi][3]);
            #pragma unroll
            for (int ni = 0; ni < 4; ni++)
                ldsm_x4(st + (boff[ni] + kk) * 4, b[ni][0], b[ni][1], b[ni][2], b[ni][3]);
            #pragma unroll
            for (int mi = 0; mi < 2; mi++)
                #pragma unroll
                for (int nj = 0; nj < 8; nj++)
                    mma_tf32(c[mi][nj][0], c[mi][nj][1], c[mi][nj][2], c[mi][nj][3],
                             a[mi][0], a[mi][1], a[mi][2], a[mi][3],
                             b[nj >> 1][2 * (nj & 1)], b[nj >> 1][2 * (nj & 1) + 1]);
        }
        if (it + 2 < nIt) issue(it + 2, (it + 2) % 3);
    }
    __syncthreads();

    // Epilogue: two 128x64 halves through smem staging
    float* Cs = (float*)gsm;
    #pragma unroll
    for (int h = 0; h < 2; h++) {
        if (wn == h) {
            #pragma unroll
            for (int mi = 0; mi < 2; mi++)
                #pragma unroll
                for (int nj = 0; nj < 8; nj++) {
                    int r  = wm * 32 + mi * 16 + (lane >> 2);
                    int cc = nj * 8 + (lane & 3) * 2;
                    *(float2*)(Cs + r * LDC + cc)       = make_float2(c[mi][nj][0], c[mi][nj][1]);
                    *(float2*)(Cs + (r + 8) * LDC + cc) = make_float2(c[mi][nj][2], c[mi][nj][3]);
                }
        }
        __syncthreads();

        #pragma unroll
        for (int e = 0; e < 32; e++) {
            int idx = tid + e * 256;
            int r   = idx >> 6;
            int cc  = idx & 63;
            float val = Cs[r * LDC + cc];
            int row = m0 + r;
            int col = n0 + h * 64 + cc;
            if (mode == 0) {
                int part = col >> 10;
                int rem  = col & 1023;
                int hh   = rem >> 6;
                int d    = rem & 63;
                int bb   = row >> 11;
                int ss   = row & 2047;
                float* dst = (part == 0) ? g_q : ((part == 1) ? g_k : g_v);
                dst[(((size_t)(bb * H_ + hh)) * S_ + ss) * HD + d] = tf32r(val);
            } else {
                Cout[(size_t)row * N + col] = val;
            }
        }
        __syncthreads();
    }
}

// ---------------------------------------------------------------------------
// Causal flash attention, FA2-style (unchanged from R9, passing).
// Q tile 128, K tile 64, 256 threads = 8 warps; softmax in registers.
// ---------------------------------------------------------------------------
#define KT   64
#define LDK  68
#define AK_OFF 0
#define AV_OFF (2 * KT * LDK)
#define AP_OFF (4 * KT * LDK)
#define A_FLOATS (AP_OFF + 8 * 16 * LDK)
#define A_SMEM_B (A_FLOATS * 4)    // 104448

__global__ __launch_bounds__(256, 2)
void attn_kernel()
{
    extern __shared__ __align__(16) float dsm[];
    float* Kbuf = dsm + AK_OFF;
    float* Vbuf = dsm + AV_OFF;

    const int q0 = blockIdx.x * 128;
    const int bh = blockIdx.y;
    const int b  = bh >> 4;
    const int h  = bh & 15;

    const float* Qg = g_q + ((size_t)bh * S_ + q0) * HD;
    const float* Kg = g_k + (size_t)bh * S_ * HD;
    const float* Vg = g_v + (size_t)bh * S_ * HD;

    const int tid  = threadIdx.x;
    const int wm   = tid >> 5;
    const int lane = tid & 31;
    float* Pw = dsm + AP_OFF + wm * (16 * LDK);

    const int qbase  = q0 + wm * 16 + (lane >> 2);
    const int c_base = (lane & 3) * 2;

    wmma::fragment<wmma::matrix_a, 16, 16, 8, wmma::precision::tf32, wmma::row_major> qf[8];
    #pragma unroll
    for (int kk = 0; kk < 8; kk++) {
        wmma::load_matrix_sync(qf[kk], Qg + (size_t)(wm * 16) * HD + kk * 8, HD);
        #pragma unroll
        for (int t = 0; t < qf[kk].num_elements; t++)
            qf[kk].x[t] = qf[kk].x[t] * 0.125f;
    }

    wmma::fragment<wmma::accumulator, 16, 16, 8, float> of[4];
    #pragma unroll
    for (int j = 0; j < 4; j++) wmma::fill_fragment(of[j], 0.0f);

    float m_st[2] = { -1e30f, -1e30f };
    float l_st[2] = { 0.0f, 0.0f };

    auto issue_kv = [&](int j0, int bufi) {
        float* Kd = Kbuf + bufi * (KT * LDK);
        float* Vd = Vbuf + bufi * (KT * LDK);
        #pragma unroll
        for (int i = 0; i < 4; i++) {
            int idx = tid + i * 256;
            int r   = idx >> 4;
            int c4  = idx & 15;
            cpasync16(Kd + r * LDK + c4 * 4, Kg + (size_t)(j0 + r) * HD + c4 * 4);
            cpasync16(Vd + r * LDK + c4 * 4, Vg + (size_t)(j0 + r) * HD + c4 * 4);
        }
    };

    const int njt = 2 * blockIdx.x + 2;
    issue_kv(0, 0);
    CP_COMMIT();

    for (int jt = 0; jt < njt; jt++) {
        const int buf = jt & 1;
        const int j0  = jt * KT;
        if (jt + 1 < njt) {
            issue_kv((jt + 1) * KT, buf ^ 1);
            CP_COMMIT();
            CP_WAIT1();
        } else {
            CP_WAIT0();
        }
        __syncthreads();

        const float* Ksh = Kbuf + buf * (KT * LDK);
        const float* Vsh = Vbuf + buf * (KT * LDK);

        wmma::fragment<wmma::accumulator, 16, 16, 8, float> sf[4];
        #pragma unroll
        for (int j = 0; j < 4; j++) wmma::fill_fragment(sf[j], 0.0f);
        #pragma unroll
        for (int kk = 0; kk < 8; kk++) {
            #pragma unroll
            for (int j = 0; j < 4; j++) {
                wmma::fragment<wmma::matrix_b, 16, 16, 8, wmma::precision::tf32, wmma::col_major> bf;
                wmma::load_matrix_sync(bf, Ksh + (j * 16) * LDK + kk * 8, LDK);
                wmma::mma_sync(sf[j], qf[kk], bf, sf[j]);
            }
        }

        float mx[2] = { -1e30f, -1e30f };
        #pragma unroll
        for (int j = 0; j < 4; j++) {
            #pragma unroll
            for (int e = 0; e < 8; e++) {
                int col = j0 + j * 16 + c_base + (e & 1) + 8 * ((e >> 2) & 1);
                int hv  = (e >> 1) & 1;
                int row = qbase + 8 * hv;
                if (col > row) sf[j].x[e] = -1e30f;
                mx[hv] = fmaxf(mx[hv], sf[j].x[e]);
            }
        }
        #pragma unroll
        for (int hv = 0; hv < 2; hv++) {
            mx[hv] = fmaxf(mx[hv], __shfl_xor_sync(0xffffffff, mx[hv], 1));
            mx[hv] = fmaxf(mx[hv], __shfl_xor_sync(0xffffffff, mx[hv], 2));
        }
        float mn[2] = { fmaxf(m_st[0], mx[0]), fmaxf(m_st[1], mx[1]) };
        float al[2] = { __expf(m_st[0] - mn[0]), __expf(m_st[1] - mn[1]) };

        float ps[2] = { 0.0f, 0.0f };
        #pragma unroll
        for (int j = 0; j < 4; j++) {
            #pragma unroll
            for (int e = 0; e < 8; e++) {
                int hv = (e >> 1) & 1;
                float p = __expf(sf[j].x[e] - mn[hv]);
                ps[hv] += p;
                sf[j].x[e] = tf32r(p);
            }
        }
        #pragma unroll
        for (int hv = 0; hv < 2; hv++) {
            ps[hv] += __shfl_xor_sync(0xffffffff, ps[hv], 1);
            ps[hv] += __shfl_xor_sync(0xffffffff, ps[hv], 2);
            l_st[hv] = l_st[hv] * al[hv] + ps[hv];
            m_st[hv] = mn[hv];
        }

        #pragma unroll
        for (int j = 0; j < 4; j++)
            #pragma unroll
            for (int e = 0; e < 8; e++)
                of[j].x[e] *= al[(e >> 1) & 1];

        #pragma unroll
        for (int j = 0; j < 4; j++)
            wmma::store_matrix_sync(Pw + j * 16, sf[j], LDK, wmma::mem_row_major);
        __syncwarp();

        #pragma unroll
        for (int kk = 0; kk < 8; kk++) {
            wmma::fragment<wmma::matrix_a, 16, 16, 8, wmma::precision::tf32, wmma::row_major> pf;
            wmma::load_matrix_sync(pf, Pw + kk * 8, LDK);
            #pragma unroll
            for (int j = 0; j < 4; j++) {
                wmma::fragment<wmma::matrix_b, 16, 16, 8, wmma::precision::tf32, wmma::row_major> vf;
                wmma::load_matrix_sync(vf, Vsh + (kk * 8) * LDK + j * 16, LDK);
                wmma::mma_sync(of[j], pf, vf, of[j]);
            }
        }
        __syncthreads();
    }

    {
        if ((lane & 3) == 0) {
            Pw[(lane >> 2) * LDK + 64]       = 1.0f / l_st[0];
            Pw[((lane >> 2) + 8) * LDK + 64] = 1.0f / l_st[1];
        }
        #pragma unroll
        for (int j = 0; j < 4; j++)
            wmma::store_matrix_sync(Pw + j * 16, of[j], LDK, wmma::mem_row_major);
        __syncwarp();

        #pragma unroll
        for (int e = 0; e < 32; e++) {
            int idx = lane + e * 32;
            int r   = idx >> 6;
            int cc  = idx & 63;
            float v = Pw[r * LDK + cc] * Pw[r * LDK + 64];
            int row = q0 + wm * 16 + r;
            g_y[((size_t)(b * S_) + row) * D_ + h * HD + cc] = tf32r(v);
        }
    }
}

// ---------------------------------------------------------------------------
extern "C" void kernel_launch(void* const* d_in, const int* in_sizes, int n_in,
                              void* d_out, int out_size)
{
    const float* x      = (const float*)d_in[0];
    const float* w_qkv  = (const float*)d_in[1];
    const float* w_proj = (const float*)d_in[2];
    float* out          = (float*)d_out;

    float *xr, *wqt, *wpt, *yr;
    cudaGetSymbolAddress((void**)&xr,  g_xr);
    cudaGetSymbolAddress((void**)&wqt, g_wqkvt);
    cudaGetSymbolAddress((void**)&wpt, g_wprojt);
    cudaGetSymbolAddress((void**)&yr,  g_y);

    cudaFuncSetAttribute(gemm_tf32_kernel,
                         cudaFuncAttributeMaxDynamicSharedMemorySize, G_SMEM_B);
    cudaFuncSetAttribute(attn_kernel,
                         cudaFuncAttributeMaxDynamicSharedMemorySize, A_SMEM_B);

    // 0) Prep: round x; transpose+round weights to [N][K]
    round_kernel<<<(M_TOT * D_ / 4 + 255) / 256, 256>>>(x, xr, M_TOT * D_ / 4);
    tround_kernel<<<dim3(3 * D_ / 32, D_ / 32), dim3(32, 8)>>>(w_qkv, wqt, D_, 3 * D_);
    tround_kernel<<<dim3(D_ / 32, D_ / 32), dim3(32, 8)>>>(w_proj, wpt, D_, D_);

    // 1) QKV GEMM + scatter
    gemm_tf32_kernel<<<dim3(3 * D_ / BN, M_TOT / BM), 256, G_SMEM_B>>>(
        xr, wqt, nullptr, 3 * D_, 0);

    // 2) Causal flash attention
    attn_kernel<<<dim3(S_ / 128, B_ * H_), 256, A_SMEM_B>>>();

    // 3) Output projection
    gemm_tf32_kernel<<<dim3(D_ / BN, M_TOT / BM), 256, G_SMEM_B>>>(
        yr, wpt, out, D_, 1);
}

// round 14
// speedup vs baseline: 3.1624x; 1.6372x over previous
#include <cuda_runtime.h>
#include <cstdint>
#include <mma.h>

using namespace nvcuda;

#define B_  4
#define S_  2048
#define D_  1024
#define H_  16
#define HD  64
#define M_TOT (B_ * S_)

// Scratch (allocation-free per harness rules)
__device__ float g_q[B_ * H_ * S_ * HD];   // [B,H,S,Hd]  tf32-rounded
__device__ float g_k[B_ * H_ * S_ * HD];   // [B,H,S,Hd]
__device__ float g_vt[B_ * H_ * HD * S_];  // [B,H,Hd,S]  (transposed V)
__device__ float g_y[M_TOT * D_];          // attention out (tf32-rounded)
__device__ float g_xr[M_TOT * D_];         // tf32-rounded x       [M][K]
__device__ float g_wqkvt[3 * D_ * D_];     // tf32-rounded w_qkv^T [N][K]
__device__ float g_wprojt[D_ * D_];        // tf32-rounded w_proj^T[N][K]

__device__ __forceinline__ float tf32r(float x) { return wmma::__float_to_tf32(x); }

__global__ __launch_bounds__(256)
void round_kernel(const float* __restrict__ in, float* __restrict__ out, int n4)
{
    int i = blockIdx.x * blockDim.x + threadIdx.x;
    if (i < n4) {
        float4 v = ((const float4*)in)[i];
        v.x = tf32r(v.x); v.y = tf32r(v.y); v.z = tf32r(v.z); v.w = tf32r(v.w);
        ((float4*)out)[i] = v;
    }
}

// in [K][N] fp32 -> out [N][K] tf32-rounded (tiled transpose)
__global__ __launch_bounds__(256)
void tround_kernel(const float* __restrict__ in, float* __restrict__ out,
                   int K, int N)
{
    __shared__ float t[32][33];
    const int n0 = blockIdx.x * 32;
    const int k0 = blockIdx.y * 32;
    const int tx = threadIdx.x, ty = threadIdx.y;
    #pragma unroll
    for (int i = 0; i < 4; i++)
        t[ty + i * 8][tx] = in[(size_t)(k0 + ty + i * 8) * N + n0 + tx];
    __syncthreads();
    #pragma unroll
    for (int i = 0; i < 4; i++)
        out[(size_t)(n0 + ty + i * 8) * K + k0 + tx] = tf32r(t[tx][ty + i * 8]);
}

// ---------------------------------------------------------------------------
__device__ __forceinline__ void cpasync16(void* smem, const void* gmem) {
    unsigned s = (unsigned)__cvta_generic_to_shared(smem);
    asm volatile("cp.async.cg.shared.global [%0], [%1], 16;\n" :: "r"(s), "l"(gmem));
}
#define CP_COMMIT() asm volatile("cp.async.commit_group;\n" ::: "memory")
#define CP_WAIT0()  asm volatile("cp.async.wait_group 0;\n" ::: "memory")
#define CP_WAIT1()  asm volatile("cp.async.wait_group 1;\n" ::: "memory")

__device__ __forceinline__ void ldsm_x4(uint32_t addr, uint32_t& r0, uint32_t& r1,
                                        uint32_t& r2, uint32_t& r3) {
    asm volatile("ldmatrix.sync.aligned.m8n8.x4.shared.b16 {%0,%1,%2,%3}, [%4];"
                 : "=r"(r0), "=r"(r1), "=r"(r2), "=r"(r3) : "r"(addr));
}

__device__ __forceinline__ void mma_tf32(float& d0, float& d1, float& d2, float& d3,
                                         uint32_t a0, uint32_t a1, uint32_t a2, uint32_t a3,
                                         uint32_t b0, uint32_t b1) {
    asm volatile(
        "mma.sync.aligned.m16n8k8.row.col.f32.tf32.tf32.f32 "
        "{%0,%1,%2,%3}, {%4,%5,%6,%7}, {%8,%9}, {%0,%1,%2,%3};"
        : "+f"(d0), "+f"(d1), "+f"(d2), "+f"(d3)
        : "r"(a0), "r"(a1), "r"(a2), "r"(a3), "r"(b0), "r"(b1));
}

// ---------------------------------------------------------------------------
// TF32 GEMM via ldmatrix + raw mma (validated R10). C = A[M,K] @ Wt[N,K]^T.
// mode 0: scatter q/k (tf32-rounded, [B,H,S,Hd]) and v transposed ([B,H,Hd,S]).
// mode 1: plain store.
// ---------------------------------------------------------------------------
#define BM 128
#define BN 128
#define BK 16
#define LDA 20
#define LDB 20
#define LDC 68
#define G_STAGE_F (BM * LDA + BN * LDB)
#define G_STAGE_B (G_STAGE_F * 4)                  // 20480
#define G_SMEM_B  (3 * G_STAGE_B)                  // 61440

__global__ __launch_bounds__(256, 2)
void gemm_tf32_kernel(const float* __restrict__ A,
                      const float* __restrict__ Wt,
                      float* __restrict__ Cout,
                      int N, int mode)
{
    extern __shared__ __align__(16) char gsm[];
    const uint32_t smem_base = (uint32_t)__cvta_generic_to_shared(gsm);
    const int K = D_;

    const int tid  = threadIdx.x;
    const int wid  = tid >> 5;
    const int lane = tid & 31;
    const int wm   = wid >> 1;
    const int wn   = wid & 1;
    const int m0   = blockIdx.y * BM;
    const int n0   = blockIdx.x * BN;

    const int a_row = (lane & 7) + 8 * ((lane >> 3) & 1);
    const int a_k   = 4 * ((lane >> 4) & 1);
    const int b_row = (lane & 7) + 8 * ((lane >> 4) & 1);
    const int b_k   = 4 * ((lane >> 3) & 1);
    int aoff[2], boff[4];
    #pragma unroll
    for (int mi = 0; mi < 2; mi++)
        aoff[mi] = (wm * 32 + mi * 16 + a_row) * LDA + a_k;
    #pragma unroll
    for (int ni = 0; ni < 4; ni++)
        boff[ni] = BM * LDA + (wn * 64 + ni * 16 + b_row) * LDB + b_k;

    float c[2][8][4];
    #pragma unroll
    for (int mi = 0; mi < 2; mi++)
        #pragma unroll
        for (int nj = 0; nj < 8; nj++)
            #pragma unroll
            for (int e = 0; e < 4; e++)
                c[mi][nj][e] = 0.0f;

    auto issue = [&](int it, int s) {
        float* As = (float*)(gsm + s * G_STAGE_B);
        float* Bs = As + BM * LDA;
        int k0 = it * BK;
        #pragma unroll
        for (int i = 0; i < 2; i++) {
            int idx = tid + i * 256;
            int r   = idx >> 2;
            int c4  = idx & 3;
            cpasync16(As + r * LDA + c4 * 4, A  + (size_t)(m0 + r) * K + k0 + c4 * 4);
        }
        #pragma unroll
        for (int i = 0; i < 2; i++) {
            int idx = tid + i * 256;
            int r   = idx >> 2;
            int c4  = idx & 3;
            cpasync16(Bs + r * LDB + c4 * 4, Wt + (size_t)(n0 + r) * K + k0 + c4 * 4);
        }
        CP_COMMIT();
    };

    const int nIt = K / BK;
    issue(0, 0);
    issue(1, 1);

    for (int it = 0; it < nIt; it++) {
        const int s = it % 3;
        if (it + 1 < nIt) CP_WAIT1(); else CP_WAIT0();
        __syncthreads();

        const uint32_t st = smem_base + s * G_STAGE_B;
        #pragma unroll
        for (int kk = 0; kk < BK; kk += 8) {
            uint32_t a[2][4], b[4][4];
            #pragma unroll
            for (int mi = 0; mi < 2; mi++)
                ldsm_x4(st + (aoff[mi] + kk) * 4, a[mi][0], a[mi][1], a[mi][2], a[mi][3]);
            #pragma unroll
            for (int ni = 0; ni < 4; ni++)
                ldsm_x4(st + (boff[ni] + kk) * 4, b[ni][0], b[ni][1], b[ni][2], b[ni][3]);
            #pragma unroll
            for (int mi = 0; mi < 2; mi++)
                #pragma unroll
                for (int nj = 0; nj < 8; nj++)
                    mma_tf32(c[mi][nj][0], c[mi][nj][1], c[mi][nj][2], c[mi][nj][3],
                             a[mi][0], a[mi][1], a[mi][2], a[mi][3],
                             b[nj >> 1][2 * (nj & 1)], b[nj >> 1][2 * (nj & 1) + 1]);
        }
        if (it + 2 < nIt) issue(it + 2, (it + 2) % 3);
    }
    __syncthreads();

    float* Cs = (float*)gsm;
    #pragma unroll
    for (int h = 0; h < 2; h++) {
        if (wn == h) {
            #pragma unroll
            for (int mi = 0; mi < 2; mi++)
                #pragma unroll
                for (int nj = 0; nj < 8; nj++) {
                    int r  = wm * 32 + mi * 16 + (lane >> 2);
                    int cc = nj * 8 + (lane & 3) * 2;
                    *(float2*)(Cs + r * LDC + cc)       = make_float2(c[mi][nj][0], c[mi][nj][1]);
                    *(float2*)(Cs + (r + 8) * LDC + cc) = make_float2(c[mi][nj][2], c[mi][nj][3]);
                }
        }
        __syncthreads();

        const int col0 = n0 + h * 64;
        if (mode == 0 && (col0 >> 10) == 2) {
            // V half-tile: transposed write -> g_vt [B,H,Hd,S], coalesced over s
            #pragma unroll
            for (int e = 0; e < 32; e++) {
                int idx = tid + e * 256;        // 0..8191
                int dl  = idx >> 7;             // 0..63 (local col)
                int sl  = idx & 127;            // 0..127 (local row)
                int col = col0 + dl;
                int rem = col & 1023;
                int hh  = rem >> 6;
                int d   = rem & 63;
                int row = m0 + sl;
                int bb  = row >> 11;
                int ss  = row & 2047;
                g_vt[(((size_t)(bb * H_ + hh)) * HD + d) * S_ + ss] =
                    tf32r(Cs[sl * LDC + dl]);
            }
        } else {
            #pragma unroll
            for (int e = 0; e < 32; e++) {
                int idx = tid + e * 256;
                int r   = idx >> 6;
                int cc  = idx & 63;
                float val = Cs[r * LDC + cc];
                int row = m0 + r;
                int col = col0 + cc;
                if (mode == 0) {
                    int part = col >> 10;       // 0 or 1 here
                    int rem  = col & 1023;
                    int hh   = rem >> 6;
                    int d    = rem & 63;
                    int bb   = row >> 11;
                    int ss   = row & 2047;
                    float* dst = (part == 0) ? g_q : g_k;
                    dst[(((size_t)(bb * H_ + hh)) * S_ + ss) * HD + d] = tf32r(val);
                } else {
                    Cout[(size_t)row * N + col] = val;
                }
            }
        }
        __syncthreads();
    }
}

// ---------------------------------------------------------------------------
// Causal flash attention, ldmatrix + raw mma. Q tile 128, K tile 64,
// 256 thr = 8 warps; warp w owns q rows [w*16, w*16+16) x all 64 key cols.
// K tile [seq][Hd] (B-operand for QK^T); V tile [Hd][seq] from g_vt (B for PV).
// P staged per-warp in smem (Q region reused), returns via ldmatrix as A.
// ---------------------------------------------------------------------------
#define KT   64
#define LDK  68
#define AK_OFF  0
#define AV_OFF  (2 * KT * LDK)
#define AQP_OFF (4 * KT * LDK)
#define A_FLOATS (AQP_OFF + 128 * LDK)
#define A_SMEM_B (A_FLOATS * 4)    // 104448

__global__ __launch_bounds__(256, 2)
void attn_kernel()
{
    extern __shared__ __align__(16) float dsm[];
    const uint32_t smem_base = (uint32_t)__cvta_generic_to_shared(dsm);

    const int q0 = blockIdx.x * 128;
    const int bh = blockIdx.y;
    const int b  = bh >> 4;
    const int h  = bh & 15;

    const float* Qg  = g_q  + ((size_t)bh * S_ + q0) * HD;
    const float* Kg  = g_k  + (size_t)bh * S_ * HD;
    const float* Vtg = g_vt + (size_t)bh * HD * S_;

    const int tid  = threadIdx.x;
    const int wm   = tid >> 5;
    const int lane = tid & 31;

    const int a_row = (lane & 7) + 8 * ((lane >> 3) & 1);
    const int a_k   = 4 * ((lane >> 4) & 1);
    const int b_row = (lane & 7) + 8 * ((lane >> 4) & 1);
    const int b_k   = 4 * ((lane >> 3) & 1);

    const int qbase  = q0 + wm * 16 + (lane >> 2);
    const int c_base = (lane & 3) * 2;

    // --- Load Q tile (128x64 = 2048 float4) into smem QP region ---
    {
        float* Qs = dsm + AQP_OFF;
        #pragma unroll
        for (int i = 0; i < 8; i++) {
            int idx = tid + i * 256;    // 0..2047
            int r   = idx >> 4;         // 0..127
            int c4  = idx & 15;         // 0..15
            cpasync16(Qs + r * LDK + c4 * 4, Qg + (size_t)r * HD + c4 * 4);
        }
        CP_COMMIT(); CP_WAIT0();
        __syncthreads();
    }
    uint32_t qa[8][4];
    {
        const uint32_t qwb = smem_base + (AQP_OFF + (wm * 16 + a_row) * LDK + a_k) * 4;
        #pragma unroll
        for (int kk = 0; kk < 8; kk++) {
            ldsm_x4(qwb + kk * 8 * 4, qa[kk][0], qa[kk][1], qa[kk][2], qa[kk][3]);
            #pragma unroll
            for (int i = 0; i < 4; i++)
                qa[kk][i] = __float_as_uint(__uint_as_float(qa[kk][i]) * 0.125f);
        }
    }
    __syncthreads();   // Q regs loaded; QP region becomes P staging

    float o[8][4];
    #pragma unroll
    for (int nj = 0; nj < 8; nj++)
        #pragma unroll
        for (int e = 0; e < 4; e++)
            o[nj][e] = 0.0f;

    float m_st[2] = { -1e30f, -1e30f };
    float l_st[2] = { 0.0f, 0.0f };

    auto issue_kv = [&](int j0, int bufi) {
        float* Kd = dsm + AK_OFF + bufi * (KT * LDK);
        float* Vd = dsm + AV_OFF + bufi * (KT * LDK);
        #pragma unroll
        for (int i = 0; i < 4; i++) {
            int idx = tid + i * 256;    // 0..1023
            int r   = idx >> 4;         // 0..63
            int c4  = idx & 15;         // 0..15
            cpasync16(Kd + r * LDK + c4 * 4, Kg  + (size_t)(j0 + r) * HD + c4 * 4);
            cpasync16(Vd + r * LDK + c4 * 4, Vtg + (size_t)r * S_ + j0 + c4 * 4);
        }
        CP_COMMIT();
    };

    const uint32_t pw_base = smem_base + (AQP_OFF + wm * 16 * LDK) * 4;
    float* Pw = dsm + AQP_OFF + wm * 16 * LDK;

    const int njt = 2 * blockIdx.x + 2;
    issue_kv(0, 0);

    for (int jt = 0; jt < njt; jt++) {
        const int buf = jt & 1;
        const int j0  = jt * KT;
        if (jt + 1 < njt) {
            issue_kv((jt + 1) * KT, buf ^ 1);
            CP_WAIT1();
        } else {
            CP_WAIT0();
        }
        __syncthreads();

        const uint32_t kst = smem_base + (AK_OFF + buf * KT * LDK) * 4;
        const uint32_t vst = smem_base + (AV_OFF + buf * KT * LDK) * 4;

        // S = (Q*scale) @ K^T : 16x64 per warp (8 n8 frags)
        float sf[8][4];
        #pragma unroll
        for (int nj = 0; nj < 8; nj++)
            #pragma unroll
            for (int e = 0; e < 4; e++)
                sf[nj][e] = 0.0f;
        #pragma unroll
        for (int kk = 0; kk < 8; kk++) {
            uint32_t kb[4][4];
            #pragma unroll
            for (int ni = 0; ni < 4; ni++)
                ldsm_x4(kst + ((ni * 16 + b_row) * LDK + b_k + kk * 8) * 4,
                        kb[ni][0], kb[ni][1], kb[ni][2], kb[ni][3]);
            #pragma unroll
            for (int nj = 0; nj < 8; nj++)
                mma_tf32(sf[nj][0], sf[nj][1], sf[nj][2], sf[nj][3],
                         qa[kk][0], qa[kk][1], qa[kk][2], qa[kk][3],
                         kb[nj >> 1][2 * (nj & 1)], kb[nj >> 1][2 * (nj & 1) + 1]);
        }

        // Causal mask + online softmax in registers
        float mx[2] = { -1e30f, -1e30f };
        #pragma unroll
        for (int nj = 0; nj < 8; nj++) {
            #pragma unroll
            for (int e = 0; e < 4; e++) {
                int col = j0 + nj * 8 + c_base + (e & 1);
                int hv  = e >> 1;
                int row = qbase + 8 * hv;
                if (col > row) sf[nj][e] = -1e30f;
                mx[hv] = fmaxf(mx[hv], sf[nj][e]);
            }
        }
        #pragma unroll
        for (int hv = 0; hv < 2; hv++) {
            mx[hv] = fmaxf(mx[hv], __shfl_xor_sync(0xffffffff, mx[hv], 1));
            mx[hv] = fmaxf(mx[hv], __shfl_xor_sync(0xffffffff, mx[hv], 2));
        }
        float mn[2] = { fmaxf(m_st[0], mx[0]), fmaxf(m_st[1], mx[1]) };
        float al[2] = { __expf(m_st[0] - mn[0]), __expf(m_st[1] - mn[1]) };

        float ps[2] = { 0.0f, 0.0f };
        #pragma unroll
        for (int nj = 0; nj < 8; nj++) {
            #pragma unroll
            for (int e = 0; e < 4; e++) {
                int hv = e >> 1;
                float p = __expf(sf[nj][e] - mn[hv]);
                ps[hv] += p;
                sf[nj][e] = tf32r(p);
            }
        }
        #pragma unroll
        for (int hv = 0; hv < 2; hv++) {
            ps[hv] += __shfl_xor_sync(0xffffffff, ps[hv], 1);
            ps[hv] += __shfl_xor_sync(0xffffffff, ps[hv], 2);
            l_st[hv] = l_st[hv] * al[hv] + ps[hv];
            m_st[hv] = mn[hv];
        }

        // Rescale O; stage P to warp-private smem; O += P @ V
        #pragma unroll
        for (int nj = 0; nj < 8; nj++)
            #pragma unroll
            for (int e = 0; e < 4; e++)
                o[nj][e] *= al[e >> 1];

        {
            int r = lane >> 2;
            #pragma unroll
            for (int nj = 0; nj < 8; nj++) {
                int cc = nj * 8 + c_base;
                *(float2*)(Pw + r * LDK + cc)       = make_float2(sf[nj][0], sf[nj][1]);
                *(float2*)(Pw + (r + 8) * LDK + cc) = make_float2(sf[nj][2], sf[nj][3]);
            }
        }
        __syncwarp();

        #pragma unroll
        for (int kk = 0; kk < 8; kk++) {
            uint32_t pa[4], vb[4][4];
            ldsm_x4(pw_base + (a_row * LDK + a_k + kk * 8) * 4,
                    pa[0], pa[1], pa[2], pa[3]);
            #pragma unroll
            for (int ni = 0; ni < 4; ni++)
                ldsm_x4(vst + ((ni * 16 + b_row) * LDK + b_k + kk * 8) * 4,
                        vb[ni][0], vb[ni][1], vb[ni][2], vb[ni][3]);
            #pragma unroll
            for (int nj = 0; nj < 8; nj++)
                mma_tf32(o[nj][0], o[nj][1], o[nj][2], o[nj][3],
                         pa[0], pa[1], pa[2], pa[3],
                         vb[nj >> 1][2 * (nj & 1)], vb[nj >> 1][2 * (nj & 1) + 1]);
        }
        __syncthreads();   // protect K/V buffers for next iteration's cp.async
    }

    // Epilogue: normalize, tf32-round, write g_y directly (float2)
    {
        float inv[2] = { 1.0f / l_st[0], 1.0f / l_st[1] };
        #pragma unroll
        for (int hv = 0; hv < 2; hv++) {
            int row = qbase + 8 * hv;
            float* dst = g_y + ((size_t)(b * S_) + row) * D_ + h * HD;
            #pragma unroll
            for (int nj = 0; nj < 8; nj++) {
                int cc = nj * 8 + c_base;
                float2 v;
                v.x = tf32r(o[nj][2 * hv + 0] * inv[hv]);
                v.y = tf32r(o[nj][2 * hv + 1] * inv[hv]);
                *(float2*)(dst + cc) = v;
            }
        }
    }
}

// ---------------------------------------------------------------------------
extern "C" void kernel_launch(void* const* d_in, const int* in_sizes, int n_in,
                              void* d_out, int out_size)
{
    const float* x      = (const float*)d_in[0];
    const float* w_qkv  = (const float*)d_in[1];
    const float* w_proj = (const float*)d_in[2];
    float* out          = (float*)d_out;

    float *xr, *wqt, *wpt, *yr;
    cudaGetSymbolAddress((void**)&xr,  g_xr);
    cudaGetSymbolAddress((void**)&wqt, g_wqkvt);
    cudaGetSymbolAddress((void**)&wpt, g_wprojt);
    cudaGetSymbolAddress((void**)&yr,  g_y);

    cudaFuncSetAttribute(gemm_tf32_kernel,
                         cudaFuncAttributeMaxDynamicSharedMemorySize, G_SMEM_B);
    cudaFuncSetAttribute(attn_kernel,
                         cudaFuncAttributeMaxDynamicSharedMemorySize, A_SMEM_B);

    // 0) Prep
    round_kernel<<<(M_TOT * D_ / 4 + 255) / 256, 256>>>(x, xr, M_TOT * D_ / 4);
    tround_kernel<<<dim3(3 * D_ / 32, D_ / 32), dim3(32, 8)>>>(w_qkv, wqt, D_, 3 * D_);
    tround_kernel<<<dim3(D_ / 32, D_ / 32), dim3(32, 8)>>>(w_proj, wpt, D_, D_);

    // 1) QKV GEMM + scatter (q,k row-major; v transposed)
    gemm_tf32_kernel<<<dim3(3 * D_ / BN, M_TOT / BM), 256, G_SMEM_B>>>(
        xr, wqt, nullptr, 3 * D_, 0);

    // 2) Causal flash attention
    attn_kernel<<<dim3(S_ / 128, B_ * H_), 256, A_SMEM_B>>>();

    // 3) Output projection
    gemm_tf32_kernel<<<dim3(D_ / BN, M_TOT / BM), 256, G_SMEM_B>>>(
        yr, wpt, out, D_, 1);
}

// round 15
// speedup vs baseline: 3.2408x; 1.0248x over previous
#include <cuda_runtime.h>
#include <cstdint>
#include <mma.h>

using namespace nvcuda;

#define B_  4
#define S_  2048
#define D_  1024
#define H_  16
#define HD  64
#define M_TOT (B_ * S_)

// Scratch (allocation-free per harness rules)
__device__ float g_q[B_ * H_ * S_ * HD];   // [B,H,S,Hd]  tf32-rounded
__device__ float g_k[B_ * H_ * S_ * HD];   // [B,H,S,Hd]
__device__ float g_vt[B_ * H_ * HD * S_];  // [B,H,Hd,S]  (transposed V)
__device__ float g_y[M_TOT * D_];          // attention out (tf32-rounded)
__device__ float g_xr[M_TOT * D_];         // tf32-rounded x       [M][K]
__device__ float g_wqkvt[3 * D_ * D_];     // tf32-rounded w_qkv^T [N][K]
__device__ float g_wprojt[D_ * D_];        // tf32-rounded w_proj^T[N][K]

__device__ __forceinline__ float tf32r(float x) { return wmma::__float_to_tf32(x); }

__global__ __launch_bounds__(256)
void round_kernel(const float* __restrict__ in, float* __restrict__ out, int n4)
{
    int i = blockIdx.x * blockDim.x + threadIdx.x;
    if (i < n4) {
        float4 v = ((const float4*)in)[i];
        v.x = tf32r(v.x); v.y = tf32r(v.y); v.z = tf32r(v.z); v.w = tf32r(v.w);
        ((float4*)out)[i] = v;
    }
}

// in [K][N] fp32 -> out [N][K] tf32-rounded (tiled transpose)
__global__ __launch_bounds__(256)
void tround_kernel(const float* __restrict__ in, float* __restrict__ out,
                   int K, int N)
{
    __shared__ float t[32][33];
    const int n0 = blockIdx.x * 32;
    const int k0 = blockIdx.y * 32;
    const int tx = threadIdx.x, ty = threadIdx.y;
    #pragma unroll
    for (int i = 0; i < 4; i++)
        t[ty + i * 8][tx] = in[(size_t)(k0 + ty + i * 8) * N + n0 + tx];
    __syncthreads();
    #pragma unroll
    for (int i = 0; i < 4; i++)
        out[(size_t)(n0 + ty + i * 8) * K + k0 + tx] = tf32r(t[tx][ty + i * 8]);
}

// ---------------------------------------------------------------------------
__device__ __forceinline__ void cpasync16(void* smem, const void* gmem) {
    unsigned s = (unsigned)__cvta_generic_to_shared(smem);
    asm volatile("cp.async.cg.shared.global [%0], [%1], 16;\n" :: "r"(s), "l"(gmem));
}
#define CP_COMMIT() asm volatile("cp.async.commit_group;\n" ::: "memory")
#define CP_WAIT0()  asm volatile("cp.async.wait_group 0;\n" ::: "memory")
#define CP_WAIT1()  asm volatile("cp.async.wait_group 1;\n" ::: "memory")

__device__ __forceinline__ void ldsm_x4(uint32_t addr, uint32_t& r0, uint32_t& r1,
                                        uint32_t& r2, uint32_t& r3) {
    asm volatile("ldmatrix.sync.aligned.m8n8.x4.shared.b16 {%0,%1,%2,%3}, [%4];"
                 : "=r"(r0), "=r"(r1), "=r"(r2), "=r"(r3) : "r"(addr));
}

__device__ __forceinline__ void mma_tf32(float& d0, float& d1, float& d2, float& d3,
                                         uint32_t a0, uint32_t a1, uint32_t a2, uint32_t a3,
                                         uint32_t b0, uint32_t b1) {
    asm volatile(
        "mma.sync.aligned.m16n8k8.row.col.f32.tf32.tf32.f32 "
        "{%0,%1,%2,%3}, {%4,%5,%6,%7}, {%8,%9}, {%0,%1,%2,%3};"
        : "+f"(d0), "+f"(d1), "+f"(d2), "+f"(d3)
        : "r"(a0), "r"(a1), "r"(a2), "r"(a3), "r"(b0), "r"(b1));
}

// ---------------------------------------------------------------------------
// TF32 GEMM via ldmatrix + raw mma. C = A[M,K] @ Wt[N,K]^T, K=1024.
// Block tile 128x128, BK=32 (was 16), 3-stage cp.async pipeline:
// 32 iterations, ONE sync per 32 k-elements (half the sync/commit overhead).
// 256 thr = 8 warps (4x2), warp tile 32x64.
// mode 0: scatter q/k ([B,H,S,Hd]) and v transposed ([B,H,Hd,S]); mode 1: store.
// ---------------------------------------------------------------------------
#define BM 128
#define BN 128
#define BK 32
#define LDA 36
#define LDB 36
#define LDC 68
#define G_STAGE_F (BM * LDA + BN * LDB)            // 9216 floats
#define G_STAGE_B (G_STAGE_F * 4)                  // 36864
#define G_SMEM_B  (3 * G_STAGE_B)                  // 110592

__global__ __launch_bounds__(256, 2)
void gemm_tf32_kernel(const float* __restrict__ A,
                      const float* __restrict__ Wt,
                      float* __restrict__ Cout,
                      int N, int mode)
{
    extern __shared__ __align__(16) char gsm[];
    const uint32_t smem_base = (uint32_t)__cvta_generic_to_shared(gsm);
    const int K = D_;

    const int tid  = threadIdx.x;
    const int wid  = tid >> 5;
    const int lane = tid & 31;
    const int wm   = wid >> 1;
    const int wn   = wid & 1;
    const int m0   = blockIdx.y * BM;
    const int n0   = blockIdx.x * BN;

    const int a_row = (lane & 7) + 8 * ((lane >> 3) & 1);
    const int a_k   = 4 * ((lane >> 4) & 1);
    const int b_row = (lane & 7) + 8 * ((lane >> 4) & 1);
    const int b_k   = 4 * ((lane >> 3) & 1);
    int aoff[2], boff[4];
    #pragma unroll
    for (int mi = 0; mi < 2; mi++)
        aoff[mi] = (wm * 32 + mi * 16 + a_row) * LDA + a_k;
    #pragma unroll
    for (int ni = 0; ni < 4; ni++)
        boff[ni] = BM * LDA + (wn * 64 + ni * 16 + b_row) * LDB + b_k;

    float c[2][8][4];
    #pragma unroll
    for (int mi = 0; mi < 2; mi++)
        #pragma unroll
        for (int nj = 0; nj < 8; nj++)
            #pragma unroll
            for (int e = 0; e < 4; e++)
                c[mi][nj][e] = 0.0f;

    auto issue = [&](int it, int s) {
        float* As = (float*)(gsm + s * G_STAGE_B);
        float* Bs = As + BM * LDA;
        int k0 = it * BK;
        #pragma unroll
        for (int i = 0; i < 4; i++) {
            int idx = tid + i * 256;    // 0..1023
            int r   = idx >> 3;         // 0..127
            int c4  = idx & 7;          // 0..7
            cpasync16(As + r * LDA + c4 * 4, A  + (size_t)(m0 + r) * K + k0 + c4 * 4);
        }
        #pragma unroll
        for (int i = 0; i < 4; i++) {
            int idx = tid + i * 256;
            int r   = idx >> 3;
            int c4  = idx & 7;
            cpasync16(Bs + r * LDB + c4 * 4, Wt + (size_t)(n0 + r) * K + k0 + c4 * 4);
        }
        CP_COMMIT();
    };

    const int nIt = K / BK;    // 32
    issue(0, 0);
    issue(1, 1);

    for (int it = 0; it < nIt; it++) {
        const int s = it % 3;
        if (it + 1 < nIt) CP_WAIT1(); else CP_WAIT0();
        __syncthreads();

        const uint32_t st = smem_base + s * G_STAGE_B;
        #pragma unroll
        for (int kk = 0; kk < BK; kk += 8) {
            uint32_t a[2][4], b[4][4];
            #pragma unroll
            for (int mi = 0; mi < 2; mi++)
                ldsm_x4(st + (aoff[mi] + kk) * 4, a[mi][0], a[mi][1], a[mi][2], a[mi][3]);
            #pragma unroll
            for (int ni = 0; ni < 4; ni++)
                ldsm_x4(st + (boff[ni] + kk) * 4, b[ni][0], b[ni][1], b[ni][2], b[ni][3]);
            #pragma unroll
            for (int mi = 0; mi < 2; mi++)
                #pragma unroll
                for (int nj = 0; nj < 8; nj++)
                    mma_tf32(c[mi][nj][0], c[mi][nj][1], c[mi][nj][2], c[mi][nj][3],
                             a[mi][0], a[mi][1], a[mi][2], a[mi][3],
                             b[nj >> 1][2 * (nj & 1)], b[nj >> 1][2 * (nj & 1) + 1]);
        }
        if (it + 2 < nIt) issue(it + 2, (it + 2) % 3);
    }
    __syncthreads();

    float* Cs = (float*)gsm;
    #pragma unroll
    for (int h = 0; h < 2; h++) {
        if (wn == h) {
            #pragma unroll
            for (int mi = 0; mi < 2; mi++)
                #pragma unroll
                for (int nj = 0; nj < 8; nj++) {
                    int r  = wm * 32 + mi * 16 + (lane >> 2);
                    int cc = nj * 8 + (lane & 3) * 2;
                    *(float2*)(Cs + r * LDC + cc)       = make_float2(c[mi][nj][0], c[mi][nj][1]);
                    *(float2*)(Cs + (r + 8) * LDC + cc) = make_float2(c[mi][nj][2], c[mi][nj][3]);
                }
        }
        __syncthreads();

        const int col0 = n0 + h * 64;
        if (mode == 0 && (col0 >> 10) == 2) {
            // V half-tile: transposed write -> g_vt [B,H,Hd,S], coalesced over s
            #pragma unroll
            for (int e = 0; e < 32; e++) {
                int idx = tid + e * 256;        // 0..8191
                int dl  = idx >> 7;             // 0..63 (local col)
                int sl  = idx & 127;            // 0..127 (local row)
                int col = col0 + dl;
                int rem = col & 1023;
                int hh  = rem >> 6;
                int d   = rem & 63;
                int row = m0 + sl;
                int bb  = row >> 11;
                int ss  = row & 2047;
                g_vt[(((size_t)(bb * H_ + hh)) * HD + d) * S_ + ss] =
                    tf32r(Cs[sl * LDC + dl]);
            }
        } else {
            #pragma unroll
            for (int e = 0; e < 32; e++) {
                int idx = tid + e * 256;
                int r   = idx >> 6;
                int cc  = idx & 63;
                float val = Cs[r * LDC + cc];
                int row = m0 + r;
                int col = col0 + cc;
                if (mode == 0) {
                    int part = col >> 10;       // 0 or 1 here
                    int rem  = col & 1023;
                    int hh   = rem >> 6;
                    int d    = rem & 63;
                    int bb   = row >> 11;
                    int ss   = row & 2047;
                    float* dst = (part == 0) ? g_q : g_k;
                    dst[(((size_t)(bb * H_ + hh)) * S_ + ss) * HD + d] = tf32r(val);
                } else {
                    Cout[(size_t)row * N + col] = val;
                }
            }
        }
        __syncthreads();
    }
}

// ---------------------------------------------------------------------------
// Causal flash attention, ldmatrix + raw mma (R14, passing — UNCHANGED).
// Q tile 128, K tile 64, 256 thr = 8 warps.
// ---------------------------------------------------------------------------
#define KT   64
#define LDK  68
#define AK_OFF  0
#define AV_OFF  (2 * KT * LDK)
#define AQP_OFF (4 * KT * LDK)
#define A_FLOATS (AQP_OFF + 128 * LDK)
#define A_SMEM_B (A_FLOATS * 4)    // 104448

__global__ __launch_bounds__(256, 2)
void attn_kernel()
{
    extern __shared__ __align__(16) float dsm[];
    const uint32_t smem_base = (uint32_t)__cvta_generic_to_shared(dsm);

    const int q0 = blockIdx.x * 128;
    const int bh = blockIdx.y;
    const int b  = bh >> 4;
    const int h  = bh & 15;

    const float* Qg  = g_q  + ((size_t)bh * S_ + q0) * HD;
    const float* Kg  = g_k  + (size_t)bh * S_ * HD;
    const float* Vtg = g_vt + (size_t)bh * HD * S_;

    const int tid  = threadIdx.x;
    const int wm   = tid >> 5;
    const int lane = tid & 31;

    const int a_row = (lane & 7) + 8 * ((lane >> 3) & 1);
    const int a_k   = 4 * ((lane >> 4) & 1);
    const int b_row = (lane & 7) + 8 * ((lane >> 4) & 1);
    const int b_k   = 4 * ((lane >> 3) & 1);

    const int qbase  = q0 + wm * 16 + (lane >> 2);
    const int c_base = (lane & 3) * 2;

    // --- Load Q tile (128x64 = 2048 float4) into smem QP region ---
    {
        float* Qs = dsm + AQP_OFF;
        #pragma unroll
        for (int i = 0; i < 8; i++) {
            int idx = tid + i * 256;    // 0..2047
            int r   = idx >> 4;         // 0..127
            int c4  = idx & 15;         // 0..15
            cpasync16(Qs + r * LDK + c4 * 4, Qg + (size_t)r * HD + c4 * 4);
        }
        CP_COMMIT(); CP_WAIT0();
        __syncthreads();
    }
    uint32_t qa[8][4];
    {
        const uint32_t qwb = smem_base + (AQP_OFF + (wm * 16 + a_row) * LDK + a_k) * 4;
        #pragma unroll
        for (int kk = 0; kk < 8; kk++) {
            ldsm_x4(qwb + kk * 8 * 4, qa[kk][0], qa[kk][1], qa[kk][2], qa[kk][3]);
            #pragma unroll
            for (int i = 0; i < 4; i++)
                qa[kk][i] = __float_as_uint(__uint_as_float(qa[kk][i]) * 0.125f);
        }
    }
    __syncthreads();   // Q regs loaded; QP region becomes P staging

    float o[8][4];
    #pragma unroll
    for (int nj = 0; nj < 8; nj++)
        #pragma unroll
        for (int e = 0; e < 4; e++)
            o[nj][e] = 0.0f;

    float m_st[2] = { -1e30f, -1e30f };
    float l_st[2] = { 0.0f, 0.0f };

    auto issue_kv = [&](int j0, int bufi) {
        float* Kd = dsm + AK_OFF + bufi * (KT * LDK);
        float* Vd = dsm + AV_OFF + bufi * (KT * LDK);
        #pragma unroll
        for (int i = 0; i < 4; i++) {
            int idx = tid + i * 256;    // 0..1023
            int r   = idx >> 4;         // 0..63
            int c4  = idx & 15;         // 0..15
            cpasync16(Kd + r * LDK + c4 * 4, Kg  + (size_t)(j0 + r) * HD + c4 * 4);
            cpasync16(Vd + r * LDK + c4 * 4, Vtg + (size_t)r * S_ + j0 + c4 * 4);
        }
        CP_COMMIT();
    };

    const uint32_t pw_base = smem_base + (AQP_OFF + wm * 16 * LDK) * 4;
    float* Pw = dsm + AQP_OFF + wm * 16 * LDK;

    const int njt = 2 * blockIdx.x + 2;
    issue_kv(0, 0);

    for (int jt = 0; jt < njt; jt++) {
        const int buf = jt & 1;
        const int j0  = jt * KT;
        if (jt + 1 < njt) {
            issue_kv((jt + 1) * KT, buf ^ 1);
            CP_WAIT1();
        } else {
            CP_WAIT0();
        }
        __syncthreads();

        const uint32_t kst = smem_base + (AK_OFF + buf * KT * LDK) * 4;
        const uint32_t vst = smem_base + (AV_OFF + buf * KT * LDK) * 4;

        // S = (Q*scale) @ K^T : 16x64 per warp (8 n8 frags)
        float sf[8][4];
        #pragma unroll
        for (int nj = 0; nj < 8; nj++)
            #pragma unroll
            for (int e = 0; e < 4; e++)
                sf[nj][e] = 0.0f;
        #pragma unroll
        for (int kk = 0; kk < 8; kk++) {
            uint32_t kb[4][4];
            #pragma unroll
            for (int ni = 0; ni < 4; ni++)
                ldsm_x4(kst + ((ni * 16 + b_row) * LDK + b_k + kk * 8) * 4,
                        kb[ni][0], kb[ni][1], kb[ni][2], kb[ni][3]);
            #pragma unroll
            for (int nj = 0; nj < 8; nj++)
                mma_tf32(sf[nj][0], sf[nj][1], sf[nj][2], sf[nj][3],
                         qa[kk][0], qa[kk][1], qa[kk][2], qa[kk][3],
                         kb[nj >> 1][2 * (nj & 1)], kb[nj >> 1][2 * (nj & 1) + 1]);
        }

        // Causal mask + online softmax in registers
        float mx[2] = { -1e30f, -1e30f };
        #pragma unroll
        for (int nj = 0; nj < 8; nj++) {
            #pragma unroll
            for (int e = 0; e < 4; e++) {
                int col = j0 + nj * 8 + c_base + (e & 1);
                int hv  = e >> 1;
                int row = qbase + 8 * hv;
                if (col > row) sf[nj][e] = -1e30f;
                mx[hv] = fmaxf(mx[hv], sf[nj][e]);
            }
        }
        #pragma unroll
        for (int hv = 0; hv < 2; hv++) {
            mx[hv] = fmaxf(mx[hv], __shfl_xor_sync(0xffffffff, mx[hv], 1));
            mx[hv] = fmaxf(mx[hv], __shfl_xor_sync(0xffffffff, mx[hv], 2));
        }
        float mn[2] = { fmaxf(m_st[0], mx[0]), fmaxf(m_st[1], mx[1]) };
        float al[2] = { __expf(m_st[0] - mn[0]), __expf(m_st[1] - mn[1]) };

        float ps[2] = { 0.0f, 0.0f };
        #pragma unroll
        for (int nj = 0; nj < 8; nj++) {
            #pragma unroll
            for (int e = 0; e < 4; e++) {
                int hv = e >> 1;
                float p = __expf(sf[nj][e] - mn[hv]);
                ps[hv] += p;
                sf[nj][e] = tf32r(p);
            }
        }
        #pragma unroll
        for (int hv = 0; hv < 2; hv++) {
            ps[hv] += __shfl_xor_sync(0xffffffff, ps[hv], 1);
            ps[hv] += __shfl_xor_sync(0xffffffff, ps[hv], 2);
            l_st[hv] = l_st[hv] * al[hv] + ps[hv];
            m_st[hv] = mn[hv];
        }

        // Rescale O; stage P to warp-private smem; O += P @ V
        #pragma unroll
        for (int nj = 0; nj < 8; nj++)
            #pragma unroll
            for (int e = 0; e < 4; e++)
                o[nj][e] *= al[e >> 1];

        {
            int r = lane >> 2;
            #pragma unroll
            for (int nj = 0; nj < 8; nj++) {
                int cc = nj * 8 + c_base;
                *(float2*)(Pw + r * LDK + cc)       = make_float2(sf[nj][0], sf[nj][1]);
                *(float2*)(Pw + (r + 8) * LDK + cc) = make_float2(sf[nj][2], sf[nj][3]);
            }
        }
        __syncwarp();

        #pragma unroll
        for (int kk = 0; kk < 8; kk++) {
            uint32_t pa[4], vb[4][4];
            ldsm_x4(pw_base + (a_row * LDK + a_k + kk * 8) * 4,
                    pa[0], pa[1], pa[2], pa[3]);
            #pragma unroll
            for (int ni = 0; ni < 4; ni++)
                ldsm_x4(vst + ((ni * 16 + b_row) * LDK + b_k + kk * 8) * 4,
                        vb[ni][0], vb[ni][1], vb[ni][2], vb[ni][3]);
            #pragma unroll
            for (int nj = 0; nj < 8; nj++)
                mma_tf32(o[nj][0], o[nj][1], o[nj][2], o[nj][3],
                         pa[0], pa[1], pa[2], pa[3],
                         vb[nj >> 1][2 * (nj & 1)], vb[nj >> 1][2 * (nj & 1) + 1]);
        }
        __syncthreads();   // protect K/V buffers for next iteration's cp.async
    }

    // Epilogue: normalize, tf32-round, write g_y directly (float2)
    {
        float inv[2] = { 1.0f / l_st[0], 1.0f / l_st[1] };
        #pragma unroll
        for (int hv = 0; hv < 2; hv++) {
            int row = qbase + 8 * hv;
            float* dst = g_y + ((size_t)(b * S_) + row) * D_ + h * HD;
            #pragma unroll
            for (int nj = 0; nj < 8; nj++) {
                int cc = nj * 8 + c_base;
                float2 v;
                v.x = tf32r(o[nj][2 * hv + 0] * inv[hv]);
                v.y = tf32r(o[nj][2 * hv + 1] * inv[hv]);
                *(float2*)(dst + cc) = v;
            }
        }
    }
}

// ---------------------------------------------------------------------------
extern "C" void kernel_launch(void* const* d_in, const int* in_sizes, int n_in,
                              void* d_out, int out_size)
{
    const float* x      = (const float*)d_in[0];
    const float* w_qkv  = (const float*)d_in[1];
    const float* w_proj = (const float*)d_in[2];
    float* out          = (float*)d_out;

    float *xr, *wqt, *wpt, *yr;
    cudaGetSymbolAddress((void**)&xr,  g_xr);
    cudaGetSymbolAddress((void**)&wqt, g_wqkvt);
    cudaGetSymbolAddress((void**)&wpt, g_wprojt);
    cudaGetSymbolAddress((void**)&yr,  g_y);

    cudaFuncSetAttribute(gemm_tf32_kernel,
                         cudaFuncAttributeMaxDynamicSharedMemorySize, G_SMEM_B);
    cudaFuncSetAttribute(attn_kernel,
                         cudaFuncAttributeMaxDynamicSharedMemorySize, A_SMEM_B);

    // 0) Prep
    round_kernel<<<(M_TOT * D_ / 4 + 255) / 256, 256>>>(x, xr, M_TOT * D_ / 4);
    tround_kernel<<<dim3(3 * D_ / 32, D_ / 32), dim3(32, 8)>>>(w_qkv, wqt, D_, 3 * D_);
    tround_kernel<<<dim3(D_ / 32, D_ / 32), dim3(32, 8)>>>(w_proj, wpt, D_, D_);

    // 1) QKV GEMM + scatter (q,k row-major; v transposed)
    gemm_tf32_kernel<<<dim3(3 * D_ / BN, M_TOT / BM), 256, G_SMEM_B>>>(
        xr, wqt, nullptr, 3 * D_, 0);

    // 2) Causal flash attention
    attn_kernel<<<dim3(S_ / 128, B_ * H_), 256, A_SMEM_B>>>();

    // 3) Output projection
    gemm_tf32_kernel<<<dim3(D_ / BN, M_TOT / BM), 256, G_SMEM_B>>>(
        yr, wpt, out, D_, 1);
}